// round 10
// baseline (speedup 1.0000x reference)
#include <cuda_runtime.h>
#include <cuda_bf16.h>
#include <math.h>

// Problem constants
#define BB   2
#define SQ   1024
#define DM   1024
#define NH   16
#define DK   64
#define DFF  2048
#define NL   4

// ---------------------------------------------------------------------------
// Scratch (device globals — no allocation allowed)
// ---------------------------------------------------------------------------
__device__ __align__(16) float g_q[BB * SQ * DM];
__device__ __align__(16) float g_k[BB * SQ * DM];
__device__ __align__(16) float g_v[BB * SQ * DM];
__device__ __align__(16) float g_x[BB * SQ * DM];
__device__ __align__(16) float g_t[BB * SQ * DM];
__device__ __align__(16) float g_h[BB * SQ * DFF];
// tf32-pre-rounded weights
__device__ __align__(16) float g_wq[NL * DM * DM];
__device__ __align__(16) float g_wk[NL * DM * DM];
__device__ __align__(16) float g_wv[NL * DM * DM];
__device__ __align__(16) float g_w1[NL * DM * DFF];
__device__ __align__(16) float g_w2[NL * DFF * DM];

// ---------------------------------------------------------------------------
// Helpers
// ---------------------------------------------------------------------------
__device__ __forceinline__ unsigned f2tf(float f) {
    unsigned u;
    asm("cvt.rna.tf32.f32 %0, %1;" : "=r"(u) : "f"(f));
    return u;
}
__device__ __forceinline__ float f2tf_f(float f) {
    return __uint_as_float(f2tf(f));
}

__device__ __forceinline__ void mma8(float* c, const unsigned* a, const unsigned* b) {
    asm volatile(
        "mma.sync.aligned.m16n8k8.row.col.f32.tf32.tf32.f32 "
        "{%0,%1,%2,%3},{%4,%5,%6,%7},{%8,%9},{%0,%1,%2,%3};\n"
        : "+f"(c[0]), "+f"(c[1]), "+f"(c[2]), "+f"(c[3])
        : "r"(a[0]), "r"(a[1]), "r"(a[2]), "r"(a[3]), "r"(b[0]), "r"(b[1]));
}

__device__ __forceinline__ void cpa16(float* smem_dst, const float* gsrc) {
    unsigned s = (unsigned)__cvta_generic_to_shared(smem_dst);
    asm volatile("cp.async.cg.shared.global [%0], [%1], 16;" :: "r"(s), "l"(gsrc));
}
__device__ __forceinline__ void cpa_commit() {
    asm volatile("cp.async.commit_group;" ::: "memory");
}
__device__ __forceinline__ void cpa_wait1() {
    asm volatile("cp.async.wait_group 1;" ::: "memory");
}
__device__ __forceinline__ void cpa_wait0() {
    asm volatile("cp.async.wait_group 0;" ::: "memory");
}

__device__ __forceinline__ float gelu_tanh_f(float x) {
    float x3 = x * x * x;
    return 0.5f * x * (1.0f + tanhf(0.7978845608028654f * (x + 0.044715f * x3)));
}

__device__ __forceinline__ float block_sum256(float v, float* sh) {
    #pragma unroll
    for (int o = 16; o; o >>= 1) v += __shfl_xor_sync(0xffffffffu, v, o);
    int w = threadIdx.x >> 5;
    if ((threadIdx.x & 31) == 0) sh[w] = v;
    __syncthreads();
    float r = (threadIdx.x < 8) ? sh[threadIdx.x] : 0.0f;
    if (threadIdx.x < 32) {
        #pragma unroll
        for (int o = 4; o; o >>= 1) r += __shfl_xor_sync(0xffffffffu, r, o);
        if (threadIdx.x == 0) sh[0] = r;
    }
    __syncthreads();
    r = sh[0];
    __syncthreads();
    return r;
}

// ---------------------------------------------------------------------------
// Weight pre-rounding: dst[i] = tf32_rna(src[i])  (float4 grid-stride)
// ---------------------------------------------------------------------------
__global__ void __launch_bounds__(256) round_w(
    const float4* __restrict__ src, float4* __restrict__ dst, int n4)
{
    for (int i = blockIdx.x * blockDim.x + threadIdx.x; i < n4;
         i += gridDim.x * blockDim.x) {
        float4 v = src[i];
        v.x = f2tf_f(v.x); v.y = f2tf_f(v.y);
        v.z = f2tf_f(v.z); v.w = f2tf_f(v.w);
        dst[i] = v;
    }
}

// ---------------------------------------------------------------------------
// tf32 tensor-core GEMM body, cp.async 2-stage pipeline.
// C[M,N] = A[M,K] * B[K,N] (+bias)(+gelu)(+round-to-tf32 on store)
// 128x128 tile, BK=32, 256 threads = 8 warps (2m x 4n), warp tile 64x32.
// CA: 1 = cvt.rna A fragments; 0 = raw bits (A already tf32-rounded).
// B fragments are ALWAYS raw bits — B must be pre-rounded.
// ---------------------------------------------------------------------------
#define GEMM_SMEM_BYTES ((2 * 128 * 36 + 2 * 32 * 132) * 4)

template<int EPI, int CA, int RND>
__device__ __forceinline__ void gemm_body(
    const float* __restrict__ A, const float* __restrict__ Bm,
    float* __restrict__ C, const float* __restrict__ bias,
    int M, int N, int K, int lda, int ldb, int ldc, float* dsm)
{
    float* As = dsm;                 // [2][128][36]
    float* Bs = dsm + 2 * 128 * 36;  // [2][32][132]

    int t = threadIdx.x;
    int lane = t & 31, w = t >> 5;
    int wm = w >> 2, wn = w & 3;     // 2 x 4 warps
    int lq = lane >> 2, lr = lane & 3;
    int row0 = blockIdx.y * 128, col0 = blockIdx.x * 128;

    float acc[4][4][4];
    #pragma unroll
    for (int i = 0; i < 4; i++)
        #pragma unroll
        for (int j = 0; j < 4; j++)
            #pragma unroll
            for (int l = 0; l < 4; l++) acc[i][j][l] = 0.0f;

    int a_row = t >> 3;             // 0..31 (x4 -> 128)
    int a_kc  = (t & 7) * 4;
    int b_kr  = t >> 5;             // 0..7 (x4 -> 32)
    int b_nc  = (t & 31) * 4;       // 0..124

    #define LOAD_TILES(s, k0)                                                   \
        {                                                                       \
            _Pragma("unroll")                                                   \
            for (int i = 0; i < 4; i++) {                                       \
                int row = a_row + i * 32;                                       \
                cpa16(&As[(s) * 4608 + row * 36 + a_kc],                        \
                      &A[(long)(row0 + row) * lda + (k0) + a_kc]);              \
            }                                                                   \
            _Pragma("unroll")                                                   \
            for (int i = 0; i < 4; i++) {                                       \
                int kr = b_kr + i * 8;                                          \
                cpa16(&Bs[(s) * 4224 + kr * 132 + b_nc],                        \
                      &Bm[(long)((k0) + kr) * ldb + col0 + b_nc]);              \
            }                                                                   \
        }

    LOAD_TILES(0, 0);
    cpa_commit();

    int KT = K >> 5;
    for (int kt = 0; kt < KT; kt++) {
        int cur = kt & 1;
        if (kt + 1 < KT) {
            LOAD_TILES(cur ^ 1, (kt + 1) * 32);
            cpa_commit();
            cpa_wait1();
        } else {
            cpa_wait0();
        }
        __syncthreads();

        const float* Ac = &As[cur * 4608];
        const float* Bc = &Bs[cur * 4224];
        #pragma unroll
        for (int ks = 0; ks < 4; ks++) {
            int kb = ks * 8;
            unsigned a[4][4], bf[4][2];
            #pragma unroll
            for (int mi = 0; mi < 4; mi++) {
                int ar = wm * 64 + mi * 16 + lq;
                if (CA) {
                    a[mi][0] = f2tf(Ac[ar * 36 + kb + lr]);
                    a[mi][1] = f2tf(Ac[(ar + 8) * 36 + kb + lr]);
                    a[mi][2] = f2tf(Ac[ar * 36 + kb + 4 + lr]);
                    a[mi][3] = f2tf(Ac[(ar + 8) * 36 + kb + 4 + lr]);
                } else {
                    a[mi][0] = __float_as_uint(Ac[ar * 36 + kb + lr]);
                    a[mi][1] = __float_as_uint(Ac[(ar + 8) * 36 + kb + lr]);
                    a[mi][2] = __float_as_uint(Ac[ar * 36 + kb + 4 + lr]);
                    a[mi][3] = __float_as_uint(Ac[(ar + 8) * 36 + kb + 4 + lr]);
                }
            }
            #pragma unroll
            for (int nj = 0; nj < 4; nj++) {
                int bn = wn * 32 + nj * 8 + lq;
                bf[nj][0] = __float_as_uint(Bc[(kb + lr) * 132 + bn]);
                bf[nj][1] = __float_as_uint(Bc[(kb + 4 + lr) * 132 + bn]);
            }
            #pragma unroll
            for (int mi = 0; mi < 4; mi++)
                #pragma unroll
                for (int nj = 0; nj < 4; nj++)
                    mma8(acc[mi][nj], a[mi], bf[nj]);
        }
        __syncthreads();
    }
    #undef LOAD_TILES

    #pragma unroll
    for (int mi = 0; mi < 4; mi++) {
        #pragma unroll
        for (int nj = 0; nj < 4; nj++) {
            int r = row0 + wm * 64 + mi * 16 + lq;
            int c = col0 + wn * 32 + nj * 8 + 2 * lr;
            float v0 = acc[mi][nj][0], v1 = acc[mi][nj][1];
            float v2 = acc[mi][nj][2], v3 = acc[mi][nj][3];
            if (EPI >= 1) {
                float b0 = bias[c], b1 = bias[c + 1];
                v0 += b0; v1 += b1; v2 += b0; v3 += b1;
            }
            if (EPI == 2) {
                v0 = gelu_tanh_f(v0); v1 = gelu_tanh_f(v1);
                v2 = gelu_tanh_f(v2); v3 = gelu_tanh_f(v3);
            }
            if (RND) {
                v0 = f2tf_f(v0); v1 = f2tf_f(v1);
                v2 = f2tf_f(v2); v3 = f2tf_f(v3);
            }
            *(float2*)&C[(long)r * ldc + c] = make_float2(v0, v1);
            *(float2*)&C[(long)(r + 8) * ldc + c] = make_float2(v2, v3);
        }
    }
}

template<int EPI, int CA, int RND>
__global__ void __launch_bounds__(256, 2) gemm_tf32(
    const float* __restrict__ A, const float* __restrict__ Bm,
    float* __restrict__ C, const float* __restrict__ bias,
    int M, int N, int K, int lda, int ldb, int ldc)
{
    extern __shared__ float dsm[];
    gemm_body<EPI, CA, RND>(A, Bm, C, bias, M, N, K, lda, ldb, ldc, dsm);
}

// Merged QKV: blockIdx.z selects which projection; outputs tf32-rounded.
__global__ void __launch_bounds__(256, 2) gemm_qkv(
    const float* __restrict__ A,
    const float* __restrict__ B0, const float* __restrict__ B1,
    const float* __restrict__ B2,
    float* __restrict__ C0, float* __restrict__ C1, float* __restrict__ C2)
{
    extern __shared__ float dsm[];
    int zz = blockIdx.z;
    const float* Bm = (zz == 0) ? B0 : (zz == 1) ? B1 : B2;
    float* C = (zz == 0) ? C0 : (zz == 1) ? C1 : C2;
    gemm_body<0, 1, 1>(A, Bm, C, nullptr, BB * SQ, DM, DM, DM, DM, DM, dsm);
}

// ---------------------------------------------------------------------------
// Fused scores + softmax + PV (flash-style, p still written to gmem).
// Block = (z, 16 q-rows) x 1024 keys. 256 threads = 8 warps.
// Phase 1: scores (warp w owns key cols [w*16,w*16+16) of each 128-key slab),
//          bias+scale+mask folded, register-resident sc[8][8].
// Phase 2: softmax normalize in regs, write p to gmem (once).
// Phase 3: o = p @ v: V streamed in 8 slabs (reusing K buffers, L2-resident),
//          p slab routed through smem Ps (tf32-rounded), per-warp n8 of o.
// grid: (SQ/16, B*NH). 2 CTAs/SM (87.5KB smem).
// ---------------------------------------------------------------------------
#define SC4_SMEM_BYTES ((16 * 68 + 2 * 128 * 68 + 16 * 132 + 128 + 128 + 1024) * 4)

__global__ void __launch_bounds__(256, 2) attn_fused(
    const float* __restrict__ q, const float* __restrict__ k,
    const float* __restrict__ v, const float* __restrict__ bias,
    const int* __restrict__ mask, float* __restrict__ p,
    float* __restrict__ o_out)
{
    extern __shared__ char smx[];
    unsigned* Qs = (unsigned*)smx;               // [16][68] tf32 bits
    float* Ks   = (float*)(Qs + 16 * 68);        // [2][128][68] K then V slabs
    float* Ps   = Ks + 2 * 128 * 68;             // [16][132] p slab (tf32)
    float* rmax = Ps + 16 * 132;                 // [16][8]
    float* rsum = rmax + 128;                    // [16][8]
    int*   msk  = (int*)(rsum + 128);            // [1024]

    int t = threadIdx.x;
    int lane = t & 31, w = t >> 5;               // 8 warps
    int lq = lane >> 2, lr = lane & 3;
    int z = blockIdx.y, b = z >> 4, h = z & 15;
    int q0 = blockIdx.x * 16;

    const float* qb = q + (long)b * SQ * DM + h * DK;
    const float* kb = k + (long)b * SQ * DM + h * DK;
    const float* vb = v + (long)b * SQ * DM + h * DK;
    const float* bz = bias + (long)z * SQ * SQ;

    // slab loader: 128 rows x 64 floats, 256 thr x 8 float4
    int k_row = t >> 4;             // 0..15 (x8 -> 128)
    int k_kc  = (t & 15) * 4;
    #define LOAD_SLAB(base, s, key0)                                            \
        {                                                                       \
            _Pragma("unroll")                                                   \
            for (int i = 0; i < 8; i++) {                                       \
                int row = k_row + i * 16;                                       \
                cpa16(&Ks[(s) * 8704 + row * 68 + k_kc],                        \
                      &base[(long)((key0) + row) * DM + k_kc]);                 \
            }                                                                   \
        }

    LOAD_SLAB(kb, 0, 0);
    cpa_commit();

    // Q tile 16x64 -> smem (already tf32-rounded; raw bits)
    {
        int row = t >> 4;
        int kc = (t & 15) * 4;
        float4 vq = *(const float4*)&qb[(long)(q0 + row) * DM + kc];
        unsigned* dst = &Qs[row * 68 + kc];
        dst[0] = __float_as_uint(vq.x); dst[1] = __float_as_uint(vq.y);
        dst[2] = __float_as_uint(vq.z); dst[3] = __float_as_uint(vq.w);
    }
    ((int4*)msk)[t] = ((const int4*)(mask + b * SQ))[t];

    float sc[8][8];
    float m0 = -3.4e38f, m1 = -3.4e38f;

    const int c0b = w * 16 + 2 * lr;
    long row_a = (long)(q0 + lq) * SQ;
    long row_b = (long)(q0 + lq + 8) * SQ;

    // ---- Phase 1: scores ----
    #pragma unroll
    for (int slab = 0; slab < 8; slab++) {
        int cur = slab & 1;
        int key0 = slab * 128;
        if (slab + 1 < 8) {
            LOAD_SLAB(kb, cur ^ 1, key0 + 128);
            cpa_commit();
        }
        int c0 = key0 + c0b;
        int c1 = c0 + 8;
        float2 B00 = *(const float2*)&bz[row_a + c0];
        float2 B01 = *(const float2*)&bz[row_a + c1];
        float2 B10 = *(const float2*)&bz[row_b + c0];
        float2 B11 = *(const float2*)&bz[row_b + c1];
        if (slab + 1 < 8) cpa_wait1(); else cpa_wait0();
        __syncthreads();

        #pragma unroll
        for (int j = 0; j < 8; j++) sc[slab][j] = 0.0f;

        const float* Kc = &Ks[cur * 8704];
        #pragma unroll
        for (int ks = 0; ks < 8; ks++) {
            int kv = ks * 8;
            unsigned a[4], bf0[2], bf1[2];
            a[0] = Qs[lq * 68 + kv + lr];
            a[1] = Qs[(lq + 8) * 68 + kv + lr];
            a[2] = Qs[lq * 68 + kv + 4 + lr];
            a[3] = Qs[(lq + 8) * 68 + kv + 4 + lr];
            int kn0 = w * 16 + lq;
            bf0[0] = __float_as_uint(Kc[kn0 * 68 + kv + lr]);
            bf0[1] = __float_as_uint(Kc[kn0 * 68 + kv + 4 + lr]);
            bf1[0] = __float_as_uint(Kc[(kn0 + 8) * 68 + kv + lr]);
            bf1[1] = __float_as_uint(Kc[(kn0 + 8) * 68 + kv + 4 + lr]);
            mma8(&sc[slab][0], a, bf0);
            mma8(&sc[slab][4], a, bf1);
        }

        int mk0a = msk[c0], mk0b = msk[c0 + 1];
        int mk1a = msk[c1], mk1b = msk[c1 + 1];
        float v0 = sc[slab][0] * 0.125f + B00.x; if (mk0a == 0) v0 = -9e15f;
        float v1 = sc[slab][1] * 0.125f + B00.y; if (mk0b == 0) v1 = -9e15f;
        float v2 = sc[slab][2] * 0.125f + B10.x; if (mk0a == 0) v2 = -9e15f;
        float v3 = sc[slab][3] * 0.125f + B10.y; if (mk0b == 0) v3 = -9e15f;
        float v4 = sc[slab][4] * 0.125f + B01.x; if (mk1a == 0) v4 = -9e15f;
        float v5 = sc[slab][5] * 0.125f + B01.y; if (mk1b == 0) v5 = -9e15f;
        float v6 = sc[slab][6] * 0.125f + B11.x; if (mk1a == 0) v6 = -9e15f;
        float v7 = sc[slab][7] * 0.125f + B11.y; if (mk1b == 0) v7 = -9e15f;
        sc[slab][0] = v0; sc[slab][1] = v1; sc[slab][2] = v2; sc[slab][3] = v3;
        sc[slab][4] = v4; sc[slab][5] = v5; sc[slab][6] = v6; sc[slab][7] = v7;
        m0 = fmaxf(m0, fmaxf(fmaxf(v0, v1), fmaxf(v4, v5)));
        m1 = fmaxf(m1, fmaxf(fmaxf(v2, v3), fmaxf(v6, v7)));
        __syncthreads();
    }

    // Prefetch V slab 0 (K buffers fully consumed)
    LOAD_SLAB(vb, 0, 0);
    cpa_commit();

    // ---- Phase 2: softmax ----
    m0 = fmaxf(m0, __shfl_xor_sync(0xffffffffu, m0, 1));
    m0 = fmaxf(m0, __shfl_xor_sync(0xffffffffu, m0, 2));
    m1 = fmaxf(m1, __shfl_xor_sync(0xffffffffu, m1, 1));
    m1 = fmaxf(m1, __shfl_xor_sync(0xffffffffu, m1, 2));
    if (lr == 0) {
        rmax[lq * 8 + w] = m0;
        rmax[(lq + 8) * 8 + w] = m1;
    }
    __syncthreads();
    float rm0 = rmax[lq * 8];
    float rm1 = rmax[(lq + 8) * 8];
    #pragma unroll
    for (int j = 1; j < 8; j++) {
        rm0 = fmaxf(rm0, rmax[lq * 8 + j]);
        rm1 = fmaxf(rm1, rmax[(lq + 8) * 8 + j]);
    }

    float s0 = 0.0f, s1 = 0.0f;
    #pragma unroll
    for (int slab = 0; slab < 8; slab++) {
        float e0 = __expf(sc[slab][0] - rm0);
        float e1 = __expf(sc[slab][1] - rm0);
        float e4 = __expf(sc[slab][4] - rm0);
        float e5 = __expf(sc[slab][5] - rm0);
        float e2 = __expf(sc[slab][2] - rm1);
        float e3 = __expf(sc[slab][3] - rm1);
        float e6 = __expf(sc[slab][6] - rm1);
        float e7 = __expf(sc[slab][7] - rm1);
        s0 += (e0 + e1) + (e4 + e5);
        s1 += (e2 + e3) + (e6 + e7);
        sc[slab][0] = e0; sc[slab][1] = e1; sc[slab][2] = e2; sc[slab][3] = e3;
        sc[slab][4] = e4; sc[slab][5] = e5; sc[slab][6] = e6; sc[slab][7] = e7;
    }
    s0 += __shfl_xor_sync(0xffffffffu, s0, 1);
    s0 += __shfl_xor_sync(0xffffffffu, s0, 2);
    s1 += __shfl_xor_sync(0xffffffffu, s1, 1);
    s1 += __shfl_xor_sync(0xffffffffu, s1, 2);
    if (lr == 0) {
        rsum[lq * 8 + w] = s0;
        rsum[(lq + 8) * 8 + w] = s1;
    }
    __syncthreads();
    float t0 = 0.0f, t1 = 0.0f;
    #pragma unroll
    for (int j = 0; j < 8; j++) {
        t0 += rsum[lq * 8 + j];
        t1 += rsum[(lq + 8) * 8 + j];
    }
    float inv0 = 1.0f / t0;
    float inv1 = 1.0f / t1;

    // normalize in regs + write p to gmem (once)
    float* pr0 = p + (long)z * SQ * SQ + row_a;
    float* pr1 = p + (long)z * SQ * SQ + row_b;
    #pragma unroll
    for (int slab = 0; slab < 8; slab++) {
        int c0 = slab * 128 + c0b;
        int c1 = c0 + 8;
        sc[slab][0] *= inv0; sc[slab][1] *= inv0;
        sc[slab][4] *= inv0; sc[slab][5] *= inv0;
        sc[slab][2] *= inv1; sc[slab][3] *= inv1;
        sc[slab][6] *= inv1; sc[slab][7] *= inv1;
        *(float2*)&pr0[c0] = make_float2(sc[slab][0], sc[slab][1]);
        *(float2*)&pr0[c1] = make_float2(sc[slab][4], sc[slab][5]);
        *(float2*)&pr1[c0] = make_float2(sc[slab][2], sc[slab][3]);
        *(float2*)&pr1[c1] = make_float2(sc[slab][6], sc[slab][7]);
    }

    // ---- Phase 3: o = p @ v ----
    float oacc[4] = {0.0f, 0.0f, 0.0f, 0.0f};
    #pragma unroll
    for (int slab = 0; slab < 8; slab++) {
        int cur = slab & 1;
        if (slab + 1 < 8) {
            LOAD_SLAB(vb, cur ^ 1, (slab + 1) * 128);
            cpa_commit();
        }
        // write this slab's p (tf32-rounded) into Ps
        {
            int c0 = c0b;
            *(float2*)&Ps[lq * 132 + c0] =
                make_float2(f2tf_f(sc[slab][0]), f2tf_f(sc[slab][1]));
            *(float2*)&Ps[lq * 132 + c0 + 8] =
                make_float2(f2tf_f(sc[slab][4]), f2tf_f(sc[slab][5]));
            *(float2*)&Ps[(lq + 8) * 132 + c0] =
                make_float2(f2tf_f(sc[slab][2]), f2tf_f(sc[slab][3]));
            *(float2*)&Ps[(lq + 8) * 132 + c0 + 8] =
                make_float2(f2tf_f(sc[slab][6]), f2tf_f(sc[slab][7]));
        }
        if (slab + 1 < 8) cpa_wait1(); else cpa_wait0();
        __syncthreads();

        const float* Vc = &Ks[cur * 8704];
        #pragma unroll
        for (int ks = 0; ks < 16; ks++) {
            int kv = ks * 8;
            unsigned a[4], bf[2];
            a[0] = __float_as_uint(Ps[lq * 132 + kv + lr]);
            a[1] = __float_as_uint(Ps[(lq + 8) * 132 + kv + lr]);
            a[2] = __float_as_uint(Ps[lq * 132 + kv + 4 + lr]);
            a[3] = __float_as_uint(Ps[(lq + 8) * 132 + kv + 4 + lr]);
            int vn = w * 8 + lq;
            bf[0] = __float_as_uint(Vc[(kv + lr) * 68 + vn]);
            bf[1] = __float_as_uint(Vc[(kv + 4 + lr) * 68 + vn]);
            mma8(oacc, a, bf);
        }
        __syncthreads();
    }
    #undef LOAD_SLAB

    // write o
    {
        float* ob = o_out + (long)b * SQ * DM + h * DK;
        int c = w * 8 + 2 * lr;
        *(float2*)&ob[(long)(q0 + lq) * DM + c] = make_float2(oacc[0], oacc[1]);
        *(float2*)&ob[(long)(q0 + lq + 8) * DM + c] = make_float2(oacc[2], oacc[3]);
    }
}

// ---------------------------------------------------------------------------
// out = LayerNorm(A + Bx) * g + b   (row length 1024, one block per row)
// ---------------------------------------------------------------------------
__global__ void __launch_bounds__(256) resid_ln(
    const float* __restrict__ A, const float* __restrict__ Bx,
    const float* __restrict__ gw, const float* __restrict__ bw,
    float* __restrict__ out)
{
    __shared__ float sh[8];
    long base = (long)blockIdx.x * DM;
    int t = threadIdx.x;
    float4 a = *(const float4*)&A[base + t * 4];
    float4 b = *(const float4*)&Bx[base + t * 4];
    float4 v = make_float4(a.x + b.x, a.y + b.y, a.z + b.z, a.w + b.w);

    float s = block_sum256(v.x + v.y + v.z + v.w, sh);
    float mu = s * (1.0f / DM);
    float dx = v.x - mu, dy = v.y - mu, dz = v.z - mu, dw = v.w - mu;
    float ss = block_sum256(dx * dx + dy * dy + dz * dz + dw * dw, sh);
    float rstd = rsqrtf(ss * (1.0f / DM) + 1e-6f);

    float4 g4 = *(const float4*)&gw[t * 4];
    float4 b4 = *(const float4*)&bw[t * 4];
    float4 o;
    o.x = dx * rstd * g4.x + b4.x;
    o.y = dy * rstd * g4.y + b4.y;
    o.z = dz * rstd * g4.z + b4.z;
    o.w = dw * rstd * g4.w + b4.w;
    *(float4*)&out[base + t * 4] = o;
}

// ---------------------------------------------------------------------------
// Launch
// ---------------------------------------------------------------------------
extern "C" void kernel_launch(void* const* d_in, const int* in_sizes, int n_in,
                              void* d_out, int out_size)
{
    const float* x_in      = (const float*)d_in[0];
    const int*   mask      = (const int*)  d_in[1];
    const float* attn_bias = (const float*)d_in[2];
    const float* Wq        = (const float*)d_in[3];
    const float* Wk        = (const float*)d_in[4];
    const float* Wv        = (const float*)d_in[5];
    const float* ln1_g     = (const float*)d_in[6];
    const float* ln1_b     = (const float*)d_in[7];
    const float* W1        = (const float*)d_in[8];
    const float* b1        = (const float*)d_in[9];
    const float* W2        = (const float*)d_in[10];
    const float* b2        = (const float*)d_in[11];
    const float* ln2_g     = (const float*)d_in[12];
    const float* ln2_b     = (const float*)d_in[13];

    float* out  = (float*)d_out;
    float* outx = out + (long)NL * BB * NH * SQ * SQ;

    float *gq, *gk, *gv, *gx, *gt, *gh;
    float *wqr, *wkr, *wvr, *w1r, *w2r;
    cudaGetSymbolAddress((void**)&gq, g_q);
    cudaGetSymbolAddress((void**)&gk, g_k);
    cudaGetSymbolAddress((void**)&gv, g_v);
    cudaGetSymbolAddress((void**)&gx, g_x);
    cudaGetSymbolAddress((void**)&gt, g_t);
    cudaGetSymbolAddress((void**)&gh, g_h);
    cudaGetSymbolAddress((void**)&wqr, g_wq);
    cudaGetSymbolAddress((void**)&wkr, g_wk);
    cudaGetSymbolAddress((void**)&wvr, g_wv);
    cudaGetSymbolAddress((void**)&w1r, g_w1);
    cudaGetSymbolAddress((void**)&w2r, g_w2);

    static int smem_set = 0;
    if (!smem_set) {
        cudaFuncSetAttribute(attn_fused,
                             cudaFuncAttributeMaxDynamicSharedMemorySize, SC4_SMEM_BYTES);
        cudaFuncSetAttribute(gemm_qkv,
                             cudaFuncAttributeMaxDynamicSharedMemorySize, GEMM_SMEM_BYTES);
        cudaFuncSetAttribute(gemm_tf32<2, 1, 1>,
                             cudaFuncAttributeMaxDynamicSharedMemorySize, GEMM_SMEM_BYTES);
        cudaFuncSetAttribute(gemm_tf32<1, 0, 0>,
                             cudaFuncAttributeMaxDynamicSharedMemorySize, GEMM_SMEM_BYTES);
        smem_set = 1;
    }

    // Pre-round all weights to tf32
    round_w<<<2048, 256>>>((const float4*)Wq, (float4*)wqr, NL * DM * DM / 4);
    round_w<<<2048, 256>>>((const float4*)Wk, (float4*)wkr, NL * DM * DM / 4);
    round_w<<<2048, 256>>>((const float4*)Wv, (float4*)wvr, NL * DM * DM / 4);
    round_w<<<2048, 256>>>((const float4*)W1, (float4*)w1r, NL * DM * DFF / 4);
    round_w<<<2048, 256>>>((const float4*)W2, (float4*)w2r, NL * DFF * DM / 4);

    cudaMemcpyAsync(gx, x_in, sizeof(float) * BB * SQ * DM, cudaMemcpyDeviceToDevice);

    dim3 blk(256);
    const int M = BB * SQ;  // 2048

    for (int n = 0; n < NL; n++) {
        float* p = out + (long)n * BB * NH * SQ * SQ;

        // QKV projections, one merged launch; outputs tf32-rounded
        gemm_qkv<<<dim3(8, 16, 3), blk, GEMM_SMEM_BYTES>>>(
            gx, wqr + (long)n * DM * DM, wkr + (long)n * DM * DM,
            wvr + (long)n * DM * DM, gq, gk, gv);

        // fused scores + softmax + PV -> p (gmem once) and o (gt)
        attn_fused<<<dim3(SQ / 16, BB * NH), blk, SC4_SMEM_BYTES>>>(
            gq, gk, gv, attn_bias, mask, p, gt);

        // x = LN(o + x)
        resid_ln<<<M, blk>>>(gt, gx, ln1_g + (long)n * DM, ln1_b + (long)n * DM, gx);

        // h = gelu(x W1 + b1); h rounded to tf32
        gemm_tf32<2, 1, 1><<<dim3(16, 16), blk, GEMM_SMEM_BYTES>>>(
            gx, w1r + (long)n * DM * DFF, gh, b1 + (long)n * DFF,
            M, DFF, DM, DM, DFF, DFF);
        // f = h W2 + b2
        gemm_tf32<1, 0, 0><<<dim3(8, 16), blk, GEMM_SMEM_BYTES>>>(
            gh, w2r + (long)n * DFF * DM, gt, b2 + (long)n * DM,
            M, DM, DFF, DFF, DM, DM);
        // x = LN(x + f)
        resid_ln<<<M, blk>>>(gx, gt, ln2_g + (long)n * DM, ln2_b + (long)n * DM, gx);
    }

    cudaMemcpyAsync(outx, gx, sizeof(float) * BB * SQ * DM, cudaMemcpyDeviceToDevice);
}

// round 11
// speedup vs baseline: 1.0426x; 1.0426x over previous
#include <cuda_runtime.h>
#include <cuda_bf16.h>
#include <math.h>

// Problem constants
#define BB   2
#define SQ   1024
#define DM   1024
#define NH   16
#define DK   64
#define DFF  2048
#define NL   4

// ---------------------------------------------------------------------------
// Scratch (device globals — no allocation allowed)
// ---------------------------------------------------------------------------
__device__ __align__(16) float g_q[BB * SQ * DM];
__device__ __align__(16) float g_k[BB * SQ * DM];
__device__ __align__(16) float g_v[BB * SQ * DM];
__device__ __align__(16) float g_x[BB * SQ * DM];
__device__ __align__(16) float g_t[BB * SQ * DM];
__device__ __align__(16) float g_h[BB * SQ * DFF];
// tf32-pre-rounded weights
__device__ __align__(16) float g_wq[NL * DM * DM];
__device__ __align__(16) float g_wk[NL * DM * DM];
__device__ __align__(16) float g_wv[NL * DM * DM];
__device__ __align__(16) float g_w1[NL * DM * DFF];
__device__ __align__(16) float g_w2[NL * DFF * DM];

// ---------------------------------------------------------------------------
// Helpers
// ---------------------------------------------------------------------------
__device__ __forceinline__ unsigned f2tf(float f) {
    unsigned u;
    asm("cvt.rna.tf32.f32 %0, %1;" : "=r"(u) : "f"(f));
    return u;
}
__device__ __forceinline__ float f2tf_f(float f) {
    return __uint_as_float(f2tf(f));
}

__device__ __forceinline__ void mma8(float* c, const unsigned* a, const unsigned* b) {
    asm volatile(
        "mma.sync.aligned.m16n8k8.row.col.f32.tf32.tf32.f32 "
        "{%0,%1,%2,%3},{%4,%5,%6,%7},{%8,%9},{%0,%1,%2,%3};\n"
        : "+f"(c[0]), "+f"(c[1]), "+f"(c[2]), "+f"(c[3])
        : "r"(a[0]), "r"(a[1]), "r"(a[2]), "r"(a[3]), "r"(b[0]), "r"(b[1]));
}

__device__ __forceinline__ void cpa16(float* smem_dst, const float* gsrc) {
    unsigned s = (unsigned)__cvta_generic_to_shared(smem_dst);
    asm volatile("cp.async.cg.shared.global [%0], [%1], 16;" :: "r"(s), "l"(gsrc));
}
__device__ __forceinline__ void cpa_commit() {
    asm volatile("cp.async.commit_group;" ::: "memory");
}
__device__ __forceinline__ void cpa_wait1() {
    asm volatile("cp.async.wait_group 1;" ::: "memory");
}
__device__ __forceinline__ void cpa_wait0() {
    asm volatile("cp.async.wait_group 0;" ::: "memory");
}

__device__ __forceinline__ float gelu_tanh_f(float x) {
    float x3 = x * x * x;
    return 0.5f * x * (1.0f + tanhf(0.7978845608028654f * (x + 0.044715f * x3)));
}

__device__ __forceinline__ float block_sum256(float v, float* sh) {
    #pragma unroll
    for (int o = 16; o; o >>= 1) v += __shfl_xor_sync(0xffffffffu, v, o);
    int w = threadIdx.x >> 5;
    if ((threadIdx.x & 31) == 0) sh[w] = v;
    __syncthreads();
    float r = (threadIdx.x < 8) ? sh[threadIdx.x] : 0.0f;
    if (threadIdx.x < 32) {
        #pragma unroll
        for (int o = 4; o; o >>= 1) r += __shfl_xor_sync(0xffffffffu, r, o);
        if (threadIdx.x == 0) sh[0] = r;
    }
    __syncthreads();
    r = sh[0];
    __syncthreads();
    return r;
}

// ---------------------------------------------------------------------------
// Weight pre-rounding: dst[i] = tf32_rna(src[i])  (float4 grid-stride)
// ---------------------------------------------------------------------------
__global__ void __launch_bounds__(256) round_w(
    const float4* __restrict__ src, float4* __restrict__ dst, int n4)
{
    for (int i = blockIdx.x * blockDim.x + threadIdx.x; i < n4;
         i += gridDim.x * blockDim.x) {
        float4 v = src[i];
        v.x = f2tf_f(v.x); v.y = f2tf_f(v.y);
        v.z = f2tf_f(v.z); v.w = f2tf_f(v.w);
        dst[i] = v;
    }
}

// ---------------------------------------------------------------------------
// tf32 tensor-core GEMM body, cp.async 2-stage pipeline.  (round-9 proven)
// C[M,N] = A[M,K] * B[K,N] (+bias)(+gelu)(+round-to-tf32 on store)
// 128x64 tile, BK=32, 256 threads = 8 warps (4m x 2n), warp tile 32x32.
// CA: 1 = cvt.rna A fragments; 0 = raw bits (A already tf32-rounded).
// B fragments always raw bits — B must be pre-rounded.
// ---------------------------------------------------------------------------
#define GEMM_SMEM_BYTES ((2 * 128 * 36 + 2 * 32 * 72) * 4)

template<int EPI, int CA, int RND>
__device__ __forceinline__ void gemm_body(
    const float* __restrict__ A, const float* __restrict__ Bm,
    float* __restrict__ C, const float* __restrict__ bias,
    int M, int N, int K, int lda, int ldb, int ldc, float* dsm)
{
    float* As = dsm;                 // [2][128][36]
    float* Bs = dsm + 2 * 128 * 36;  // [2][32][72]

    int t = threadIdx.x;
    int lane = t & 31, w = t >> 5;
    int wm = w >> 1, wn = w & 1;
    int lq = lane >> 2, lr = lane & 3;
    int row0 = blockIdx.y * 128, col0 = blockIdx.x * 64;

    float acc[2][4][4];
    #pragma unroll
    for (int i = 0; i < 2; i++)
        #pragma unroll
        for (int j = 0; j < 4; j++)
            #pragma unroll
            for (int l = 0; l < 4; l++) acc[i][j][l] = 0.0f;

    int a_row = t >> 3;             // 0..31 (x4 -> 128)
    int a_kc  = (t & 7) * 4;
    int b_kr  = t >> 4;             // 0..15 (x2 -> 32)
    int b_nc  = (t & 15) * 4;

    #define LOAD_TILES(s, k0)                                                   \
        {                                                                       \
            _Pragma("unroll")                                                   \
            for (int i = 0; i < 4; i++) {                                       \
                int row = a_row + i * 32;                                       \
                cpa16(&As[(s) * 4608 + row * 36 + a_kc],                        \
                      &A[(long)(row0 + row) * lda + (k0) + a_kc]);              \
            }                                                                   \
            _Pragma("unroll")                                                   \
            for (int i = 0; i < 2; i++) {                                       \
                int kr = b_kr + i * 16;                                         \
                cpa16(&Bs[(s) * 2304 + kr * 72 + b_nc],                         \
                      &Bm[(long)((k0) + kr) * ldb + col0 + b_nc]);              \
            }                                                                   \
        }

    LOAD_TILES(0, 0);
    cpa_commit();

    int KT = K >> 5;
    for (int kt = 0; kt < KT; kt++) {
        int cur = kt & 1;
        if (kt + 1 < KT) {
            LOAD_TILES(cur ^ 1, (kt + 1) * 32);
            cpa_commit();
            cpa_wait1();
        } else {
            cpa_wait0();
        }
        __syncthreads();

        const float* Ac = &As[cur * 4608];
        const float* Bc = &Bs[cur * 2304];
        #pragma unroll
        for (int ks = 0; ks < 4; ks++) {
            int kb = ks * 8;
            unsigned a[2][4], bf[4][2];
            #pragma unroll
            for (int mi = 0; mi < 2; mi++) {
                int ar = wm * 32 + mi * 16 + lq;
                if (CA) {
                    a[mi][0] = f2tf(Ac[ar * 36 + kb + lr]);
                    a[mi][1] = f2tf(Ac[(ar + 8) * 36 + kb + lr]);
                    a[mi][2] = f2tf(Ac[ar * 36 + kb + 4 + lr]);
                    a[mi][3] = f2tf(Ac[(ar + 8) * 36 + kb + 4 + lr]);
                } else {
                    a[mi][0] = __float_as_uint(Ac[ar * 36 + kb + lr]);
                    a[mi][1] = __float_as_uint(Ac[(ar + 8) * 36 + kb + lr]);
                    a[mi][2] = __float_as_uint(Ac[ar * 36 + kb + 4 + lr]);
                    a[mi][3] = __float_as_uint(Ac[(ar + 8) * 36 + kb + 4 + lr]);
                }
            }
            #pragma unroll
            for (int nj = 0; nj < 4; nj++) {
                int bn = wn * 32 + nj * 8 + lq;
                bf[nj][0] = __float_as_uint(Bc[(kb + lr) * 72 + bn]);
                bf[nj][1] = __float_as_uint(Bc[(kb + 4 + lr) * 72 + bn]);
            }
            #pragma unroll
            for (int mi = 0; mi < 2; mi++)
                #pragma unroll
                for (int nj = 0; nj < 4; nj++)
                    mma8(acc[mi][nj], a[mi], bf[nj]);
        }
        __syncthreads();
    }
    #undef LOAD_TILES

    #pragma unroll
    for (int mi = 0; mi < 2; mi++) {
        #pragma unroll
        for (int nj = 0; nj < 4; nj++) {
            int r = row0 + wm * 32 + mi * 16 + lq;
            int c = col0 + wn * 32 + nj * 8 + 2 * lr;
            float v0 = acc[mi][nj][0], v1 = acc[mi][nj][1];
            float v2 = acc[mi][nj][2], v3 = acc[mi][nj][3];
            if (EPI >= 1) {
                float b0 = bias[c], b1 = bias[c + 1];
                v0 += b0; v1 += b1; v2 += b0; v3 += b1;
            }
            if (EPI == 2) {
                v0 = gelu_tanh_f(v0); v1 = gelu_tanh_f(v1);
                v2 = gelu_tanh_f(v2); v3 = gelu_tanh_f(v3);
            }
            if (RND) {
                v0 = f2tf_f(v0); v1 = f2tf_f(v1);
                v2 = f2tf_f(v2); v3 = f2tf_f(v3);
            }
            *(float2*)&C[(long)r * ldc + c] = make_float2(v0, v1);
            *(float2*)&C[(long)(r + 8) * ldc + c] = make_float2(v2, v3);
        }
    }
}

template<int EPI, int CA, int RND>
__global__ void __launch_bounds__(256) gemm_tf32(
    const float* __restrict__ A, const float* __restrict__ Bm,
    float* __restrict__ C, const float* __restrict__ bias,
    int M, int N, int K, int lda, int ldb, int ldc)
{
    extern __shared__ float dsm[];
    gemm_body<EPI, CA, RND>(A, Bm, C, bias, M, N, K, lda, ldb, ldc, dsm);
}

// Merged QKV: blockIdx.z selects which projection; outputs tf32-rounded.
__global__ void __launch_bounds__(256) gemm_qkv(
    const float* __restrict__ A,
    const float* __restrict__ B0, const float* __restrict__ B1,
    const float* __restrict__ B2,
    float* __restrict__ C0, float* __restrict__ C1, float* __restrict__ C2)
{
    extern __shared__ float dsm[];
    int zz = blockIdx.z;
    const float* Bm = (zz == 0) ? B0 : (zz == 1) ? B1 : B2;
    float* C = (zz == 0) ? C0 : (zz == 1) ? C1 : C2;
    gemm_body<0, 1, 1>(A, Bm, C, nullptr, BB * SQ, DM, DM, DM, DM, DM, dsm);
}

// ---------------------------------------------------------------------------
// Fused scores + softmax + PV (flash-style, p written to gmem once).
// Block = (z, 16 q-rows) x 1024 keys. 256 threads = 8 warps.
// K slabs stored at stride 68 (access (4lq+lr): conflict-free).
// V slabs stored at stride 72 (access (8lr+lq): conflict-free).
// Stage size = max(128*68, 128*72) = 9216 floats.
// grid: (SQ/16, B*NH). 2 CTAs/SM (~91.6KB smem).
// ---------------------------------------------------------------------------
#define SC4_STAGE 9216
#define SC4_SMEM_BYTES ((16 * 68 + 2 * SC4_STAGE + 16 * 132 + 128 + 128 + 1024) * 4)

__global__ void __launch_bounds__(256, 2) attn_fused(
    const float* __restrict__ q, const float* __restrict__ k,
    const float* __restrict__ v, const float* __restrict__ bias,
    const int* __restrict__ mask, float* __restrict__ p,
    float* __restrict__ o_out)
{
    extern __shared__ char smx[];
    unsigned* Qs = (unsigned*)smx;               // [16][68] tf32 bits
    float* Ks   = (float*)(Qs + 16 * 68);        // [2][SC4_STAGE] K(68)/V(72)
    float* Ps   = Ks + 2 * SC4_STAGE;            // [16][132] p slab (tf32)
    float* rmax = Ps + 16 * 132;                 // [16][8]
    float* rsum = rmax + 128;                    // [16][8]
    int*   msk  = (int*)(rsum + 128);            // [1024]

    int t = threadIdx.x;
    int lane = t & 31, w = t >> 5;               // 8 warps
    int lq = lane >> 2, lr = lane & 3;
    int z = blockIdx.y, b = z >> 4, h = z & 15;
    int q0 = blockIdx.x * 16;

    const float* qb = q + (long)b * SQ * DM + h * DK;
    const float* kb = k + (long)b * SQ * DM + h * DK;
    const float* vb = v + (long)b * SQ * DM + h * DK;
    const float* bz = bias + (long)z * SQ * SQ;

    // slab loaders: 128 rows x 64 floats, 256 thr x 8 float4
    int k_row = t >> 4;             // 0..15 (x8 -> 128)
    int k_kc  = (t & 15) * 4;
    #define LOAD_SLAB(base, s, key0, stride)                                    \
        {                                                                       \
            _Pragma("unroll")                                                   \
            for (int i = 0; i < 8; i++) {                                       \
                int row = k_row + i * 16;                                       \
                cpa16(&Ks[(s) * SC4_STAGE + row * (stride) + k_kc],             \
                      &base[(long)((key0) + row) * DM + k_kc]);                 \
            }                                                                   \
        }

    LOAD_SLAB(kb, 0, 0, 68);
    cpa_commit();

    // Q tile 16x64 -> smem (already tf32-rounded; raw bits)
    {
        int row = t >> 4;
        int kc = (t & 15) * 4;
        float4 vq = *(const float4*)&qb[(long)(q0 + row) * DM + kc];
        unsigned* dst = &Qs[row * 68 + kc];
        dst[0] = __float_as_uint(vq.x); dst[1] = __float_as_uint(vq.y);
        dst[2] = __float_as_uint(vq.z); dst[3] = __float_as_uint(vq.w);
    }
    ((int4*)msk)[t] = ((const int4*)(mask + b * SQ))[t];

    float sc[8][8];
    float m0 = -3.4e38f, m1 = -3.4e38f;

    const int c0b = w * 16 + 2 * lr;
    long row_a = (long)(q0 + lq) * SQ;
    long row_b = (long)(q0 + lq + 8) * SQ;

    // ---- Phase 1: scores ----
    #pragma unroll
    for (int slab = 0; slab < 8; slab++) {
        int cur = slab & 1;
        int key0 = slab * 128;
        if (slab + 1 < 8) {
            LOAD_SLAB(kb, cur ^ 1, key0 + 128, 68);
            cpa_commit();
        }
        int c0 = key0 + c0b;
        int c1 = c0 + 8;
        float2 B00 = *(const float2*)&bz[row_a + c0];
        float2 B01 = *(const float2*)&bz[row_a + c1];
        float2 B10 = *(const float2*)&bz[row_b + c0];
        float2 B11 = *(const float2*)&bz[row_b + c1];
        if (slab + 1 < 8) cpa_wait1(); else cpa_wait0();
        __syncthreads();

        #pragma unroll
        for (int j = 0; j < 8; j++) sc[slab][j] = 0.0f;

        const float* Kc = &Ks[cur * SC4_STAGE];
        #pragma unroll
        for (int ks = 0; ks < 8; ks++) {
            int kv = ks * 8;
            unsigned a[4], bf0[2], bf1[2];
            a[0] = Qs[lq * 68 + kv + lr];
            a[1] = Qs[(lq + 8) * 68 + kv + lr];
            a[2] = Qs[lq * 68 + kv + 4 + lr];
            a[3] = Qs[(lq + 8) * 68 + kv + 4 + lr];
            int kn0 = w * 16 + lq;
            bf0[0] = __float_as_uint(Kc[kn0 * 68 + kv + lr]);
            bf0[1] = __float_as_uint(Kc[kn0 * 68 + kv + 4 + lr]);
            bf1[0] = __float_as_uint(Kc[(kn0 + 8) * 68 + kv + lr]);
            bf1[1] = __float_as_uint(Kc[(kn0 + 8) * 68 + kv + 4 + lr]);
            mma8(&sc[slab][0], a, bf0);
            mma8(&sc[slab][4], a, bf1);
        }

        int mk0a = msk[c0], mk0b = msk[c0 + 1];
        int mk1a = msk[c1], mk1b = msk[c1 + 1];
        float v0 = sc[slab][0] * 0.125f + B00.x; if (mk0a == 0) v0 = -9e15f;
        float v1 = sc[slab][1] * 0.125f + B00.y; if (mk0b == 0) v1 = -9e15f;
        float v2 = sc[slab][2] * 0.125f + B10.x; if (mk0a == 0) v2 = -9e15f;
        float v3 = sc[slab][3] * 0.125f + B10.y; if (mk0b == 0) v3 = -9e15f;
        float v4 = sc[slab][4] * 0.125f + B01.x; if (mk1a == 0) v4 = -9e15f;
        float v5 = sc[slab][5] * 0.125f + B01.y; if (mk1b == 0) v5 = -9e15f;
        float v6 = sc[slab][6] * 0.125f + B11.x; if (mk1a == 0) v6 = -9e15f;
        float v7 = sc[slab][7] * 0.125f + B11.y; if (mk1b == 0) v7 = -9e15f;
        sc[slab][0] = v0; sc[slab][1] = v1; sc[slab][2] = v2; sc[slab][3] = v3;
        sc[slab][4] = v4; sc[slab][5] = v5; sc[slab][6] = v6; sc[slab][7] = v7;
        m0 = fmaxf(m0, fmaxf(fmaxf(v0, v1), fmaxf(v4, v5)));
        m1 = fmaxf(m1, fmaxf(fmaxf(v2, v3), fmaxf(v6, v7)));
        __syncthreads();
    }

    // Prefetch V slab 0 (K buffers fully consumed)
    LOAD_SLAB(vb, 0, 0, 72);
    cpa_commit();

    // ---- Phase 2: softmax ----
    m0 = fmaxf(m0, __shfl_xor_sync(0xffffffffu, m0, 1));
    m0 = fmaxf(m0, __shfl_xor_sync(0xffffffffu, m0, 2));
    m1 = fmaxf(m1, __shfl_xor_sync(0xffffffffu, m1, 1));
    m1 = fmaxf(m1, __shfl_xor_sync(0xffffffffu, m1, 2));
    if (lr == 0) {
        rmax[lq * 8 + w] = m0;
        rmax[(lq + 8) * 8 + w] = m1;
    }
    __syncthreads();
    float rm0 = rmax[lq * 8];
    float rm1 = rmax[(lq + 8) * 8];
    #pragma unroll
    for (int j = 1; j < 8; j++) {
        rm0 = fmaxf(rm0, rmax[lq * 8 + j]);
        rm1 = fmaxf(rm1, rmax[(lq + 8) * 8 + j]);
    }

    float s0 = 0.0f, s1 = 0.0f;
    #pragma unroll
    for (int slab = 0; slab < 8; slab++) {
        float e0 = __expf(sc[slab][0] - rm0);
        float e1 = __expf(sc[slab][1] - rm0);
        float e4 = __expf(sc[slab][4] - rm0);
        float e5 = __expf(sc[slab][5] - rm0);
        float e2 = __expf(sc[slab][2] - rm1);
        float e3 = __expf(sc[slab][3] - rm1);
        float e6 = __expf(sc[slab][6] - rm1);
        float e7 = __expf(sc[slab][7] - rm1);
        s0 += (e0 + e1) + (e4 + e5);
        s1 += (e2 + e3) + (e6 + e7);
        sc[slab][0] = e0; sc[slab][1] = e1; sc[slab][2] = e2; sc[slab][3] = e3;
        sc[slab][4] = e4; sc[slab][5] = e5; sc[slab][6] = e6; sc[slab][7] = e7;
    }
    s0 += __shfl_xor_sync(0xffffffffu, s0, 1);
    s0 += __shfl_xor_sync(0xffffffffu, s0, 2);
    s1 += __shfl_xor_sync(0xffffffffu, s1, 1);
    s1 += __shfl_xor_sync(0xffffffffu, s1, 2);
    if (lr == 0) {
        rsum[lq * 8 + w] = s0;
        rsum[(lq + 8) * 8 + w] = s1;
    }
    __syncthreads();
    float t0 = 0.0f, t1 = 0.0f;
    #pragma unroll
    for (int j = 0; j < 8; j++) {
        t0 += rsum[lq * 8 + j];
        t1 += rsum[(lq + 8) * 8 + j];
    }
    float inv0 = 1.0f / t0;
    float inv1 = 1.0f / t1;

    // normalize in regs + write p to gmem (once)
    float* pr0 = p + (long)z * SQ * SQ + row_a;
    float* pr1 = p + (long)z * SQ * SQ + row_b;
    #pragma unroll
    for (int slab = 0; slab < 8; slab++) {
        int c0 = slab * 128 + c0b;
        int c1 = c0 + 8;
        sc[slab][0] *= inv0; sc[slab][1] *= inv0;
        sc[slab][4] *= inv0; sc[slab][5] *= inv0;
        sc[slab][2] *= inv1; sc[slab][3] *= inv1;
        sc[slab][6] *= inv1; sc[slab][7] *= inv1;
        *(float2*)&pr0[c0] = make_float2(sc[slab][0], sc[slab][1]);
        *(float2*)&pr0[c1] = make_float2(sc[slab][4], sc[slab][5]);
        *(float2*)&pr1[c0] = make_float2(sc[slab][2], sc[slab][3]);
        *(float2*)&pr1[c1] = make_float2(sc[slab][6], sc[slab][7]);
    }

    // ---- Phase 3: o = p @ v ----
    float oacc[4] = {0.0f, 0.0f, 0.0f, 0.0f};
    #pragma unroll
    for (int slab = 0; slab < 8; slab++) {
        int cur = slab & 1;
        if (slab + 1 < 8) {
            LOAD_SLAB(vb, cur ^ 1, (slab + 1) * 128, 72);
            cpa_commit();
        }
        // stage this slab's p (tf32-rounded) into Ps
        {
            int c0 = c0b;
            *(float2*)&Ps[lq * 132 + c0] =
                make_float2(f2tf_f(sc[slab][0]), f2tf_f(sc[slab][1]));
            *(float2*)&Ps[lq * 132 + c0 + 8] =
                make_float2(f2tf_f(sc[slab][4]), f2tf_f(sc[slab][5]));
            *(float2*)&Ps[(lq + 8) * 132 + c0] =
                make_float2(f2tf_f(sc[slab][2]), f2tf_f(sc[slab][3]));
            *(float2*)&Ps[(lq + 8) * 132 + c0 + 8] =
                make_float2(f2tf_f(sc[slab][6]), f2tf_f(sc[slab][7]));
        }
        if (slab + 1 < 8) cpa_wait1(); else cpa_wait0();
        __syncthreads();

        const float* Vc = &Ks[cur * SC4_STAGE];
        #pragma unroll
        for (int ks = 0; ks < 16; ks++) {
            int kv = ks * 8;
            unsigned a[4], bf[2];
            a[0] = __float_as_uint(Ps[lq * 132 + kv + lr]);
            a[1] = __float_as_uint(Ps[(lq + 8) * 132 + kv + lr]);
            a[2] = __float_as_uint(Ps[lq * 132 + kv + 4 + lr]);
            a[3] = __float_as_uint(Ps[(lq + 8) * 132 + kv + 4 + lr]);
            int vn = w * 8 + lq;
            bf[0] = __float_as_uint(Vc[(kv + lr) * 72 + vn]);
            bf[1] = __float_as_uint(Vc[(kv + 4 + lr) * 72 + vn]);
            mma8(oacc, a, bf);
        }
        __syncthreads();
    }
    #undef LOAD_SLAB

    // write o
    {
        float* ob = o_out + (long)b * SQ * DM + h * DK;
        int c = w * 8 + 2 * lr;
        *(float2*)&ob[(long)(q0 + lq) * DM + c] = make_float2(oacc[0], oacc[1]);
        *(float2*)&ob[(long)(q0 + lq + 8) * DM + c] = make_float2(oacc[2], oacc[3]);
    }
}

// ---------------------------------------------------------------------------
// out = LayerNorm(A + Bx) * g + b   (row length 1024, one block per row)
// ---------------------------------------------------------------------------
__global__ void __launch_bounds__(256) resid_ln(
    const float* __restrict__ A, const float* __restrict__ Bx,
    const float* __restrict__ gw, const float* __restrict__ bw,
    float* __restrict__ out)
{
    __shared__ float sh[8];
    long base = (long)blockIdx.x * DM;
    int t = threadIdx.x;
    float4 a = *(const float4*)&A[base + t * 4];
    float4 b = *(const float4*)&Bx[base + t * 4];
    float4 v = make_float4(a.x + b.x, a.y + b.y, a.z + b.z, a.w + b.w);

    float s = block_sum256(v.x + v.y + v.z + v.w, sh);
    float mu = s * (1.0f / DM);
    float dx = v.x - mu, dy = v.y - mu, dz = v.z - mu, dw = v.w - mu;
    float ss = block_sum256(dx * dx + dy * dy + dz * dz + dw * dw, sh);
    float rstd = rsqrtf(ss * (1.0f / DM) + 1e-6f);

    float4 g4 = *(const float4*)&gw[t * 4];
    float4 b4 = *(const float4*)&bw[t * 4];
    float4 o;
    o.x = dx * rstd * g4.x + b4.x;
    o.y = dy * rstd * g4.y + b4.y;
    o.z = dz * rstd * g4.z + b4.z;
    o.w = dw * rstd * g4.w + b4.w;
    *(float4*)&out[base + t * 4] = o;
}

// ---------------------------------------------------------------------------
// Launch
// ---------------------------------------------------------------------------
extern "C" void kernel_launch(void* const* d_in, const int* in_sizes, int n_in,
                              void* d_out, int out_size)
{
    const float* x_in      = (const float*)d_in[0];
    const int*   mask      = (const int*)  d_in[1];
    const float* attn_bias = (const float*)d_in[2];
    const float* Wq        = (const float*)d_in[3];
    const float* Wk        = (const float*)d_in[4];
    const float* Wv        = (const float*)d_in[5];
    const float* ln1_g     = (const float*)d_in[6];
    const float* ln1_b     = (const float*)d_in[7];
    const float* W1        = (const float*)d_in[8];
    const float* b1        = (const float*)d_in[9];
    const float* W2        = (const float*)d_in[10];
    const float* b2        = (const float*)d_in[11];
    const float* ln2_g     = (const float*)d_in[12];
    const float* ln2_b     = (const float*)d_in[13];

    float* out  = (float*)d_out;
    float* outx = out + (long)NL * BB * NH * SQ * SQ;

    float *gq, *gk, *gv, *gx, *gt, *gh;
    float *wqr, *wkr, *wvr, *w1r, *w2r;
    cudaGetSymbolAddress((void**)&gq, g_q);
    cudaGetSymbolAddress((void**)&gk, g_k);
    cudaGetSymbolAddress((void**)&gv, g_v);
    cudaGetSymbolAddress((void**)&gx, g_x);
    cudaGetSymbolAddress((void**)&gt, g_t);
    cudaGetSymbolAddress((void**)&gh, g_h);
    cudaGetSymbolAddress((void**)&wqr, g_wq);
    cudaGetSymbolAddress((void**)&wkr, g_wk);
    cudaGetSymbolAddress((void**)&wvr, g_wv);
    cudaGetSymbolAddress((void**)&w1r, g_w1);
    cudaGetSymbolAddress((void**)&w2r, g_w2);

    static int smem_set = 0;
    if (!smem_set) {
        cudaFuncSetAttribute(attn_fused,
                             cudaFuncAttributeMaxDynamicSharedMemorySize, SC4_SMEM_BYTES);
        cudaFuncSetAttribute(gemm_qkv,
                             cudaFuncAttributeMaxDynamicSharedMemorySize, GEMM_SMEM_BYTES);
        cudaFuncSetAttribute(gemm_tf32<2, 1, 1>,
                             cudaFuncAttributeMaxDynamicSharedMemorySize, GEMM_SMEM_BYTES);
        cudaFuncSetAttribute(gemm_tf32<1, 0, 0>,
                             cudaFuncAttributeMaxDynamicSharedMemorySize, GEMM_SMEM_BYTES);
        smem_set = 1;
    }

    // Pre-round all weights to tf32
    round_w<<<2048, 256>>>((const float4*)Wq, (float4*)wqr, NL * DM * DM / 4);
    round_w<<<2048, 256>>>((const float4*)Wk, (float4*)wkr, NL * DM * DM / 4);
    round_w<<<2048, 256>>>((const float4*)Wv, (float4*)wvr, NL * DM * DM / 4);
    round_w<<<2048, 256>>>((const float4*)W1, (float4*)w1r, NL * DM * DFF / 4);
    round_w<<<2048, 256>>>((const float4*)W2, (float4*)w2r, NL * DFF * DM / 4);

    cudaMemcpyAsync(gx, x_in, sizeof(float) * BB * SQ * DM, cudaMemcpyDeviceToDevice);

    dim3 blk(256);
    const int M = BB * SQ;  // 2048

    for (int n = 0; n < NL; n++) {
        float* p = out + (long)n * BB * NH * SQ * SQ;

        // QKV projections, one merged launch; outputs tf32-rounded
        gemm_qkv<<<dim3(16, 16, 3), blk, GEMM_SMEM_BYTES>>>(
            gx, wqr + (long)n * DM * DM, wkr + (long)n * DM * DM,
            wvr + (long)n * DM * DM, gq, gk, gv);

        // fused scores + softmax + PV -> p (gmem once) and o (gt)
        attn_fused<<<dim3(SQ / 16, BB * NH), blk, SC4_SMEM_BYTES>>>(
            gq, gk, gv, attn_bias, mask, p, gt);

        // x = LN(o + x)
        resid_ln<<<M, blk>>>(gt, gx, ln1_g + (long)n * DM, ln1_b + (long)n * DM, gx);

        // h = gelu(x W1 + b1); h rounded to tf32
        gemm_tf32<2, 1, 1><<<dim3(32, 16), blk, GEMM_SMEM_BYTES>>>(
            gx, w1r + (long)n * DM * DFF, gh, b1 + (long)n * DFF,
            M, DFF, DM, DM, DFF, DFF);
        // f = h W2 + b2
        gemm_tf32<1, 0, 0><<<dim3(16, 16), blk, GEMM_SMEM_BYTES>>>(
            gh, w2r + (long)n * DFF * DM, gt, b2 + (long)n * DM,
            M, DM, DFF, DFF, DM, DM);
        // x = LN(x + f)
        resid_ln<<<M, blk>>>(gx, gt, ln2_g + (long)n * DM, ln2_b + (long)n * DM, gx);
    }

    cudaMemcpyAsync(outx, gx, sizeof(float) * BB * SQ * DM, cudaMemcpyDeviceToDevice);
}

// round 12
// speedup vs baseline: 1.1685x; 1.1208x over previous
#include <cuda_runtime.h>
#include <cuda_bf16.h>
#include <math.h>

// Problem constants
#define BB   2
#define SQ   1024
#define DM   1024
#define NH   16
#define DK   64
#define DFF  2048
#define NL   4

// ---------------------------------------------------------------------------
// Scratch (device globals — no allocation allowed)
// ---------------------------------------------------------------------------
__device__ __align__(16) float g_q[BB * SQ * DM];
__device__ __align__(16) float g_k[BB * SQ * DM];
__device__ __align__(16) float g_v[BB * SQ * DM];
__device__ __align__(16) float g_x[BB * SQ * DM];
__device__ __align__(16) float g_t[BB * SQ * DM];
__device__ __align__(16) float g_h[BB * SQ * DFF];
// tf32-pre-rounded weights
__device__ __align__(16) float g_wq[NL * DM * DM];
__device__ __align__(16) float g_wk[NL * DM * DM];
__device__ __align__(16) float g_wv[NL * DM * DM];
__device__ __align__(16) float g_w1[NL * DM * DFF];
__device__ __align__(16) float g_w2[NL * DFF * DM];

// ---------------------------------------------------------------------------
// Helpers
// ---------------------------------------------------------------------------
__device__ __forceinline__ unsigned f2tf(float f) {
    unsigned u;
    asm("cvt.rna.tf32.f32 %0, %1;" : "=r"(u) : "f"(f));
    return u;
}
__device__ __forceinline__ float f2tf_f(float f) {
    return __uint_as_float(f2tf(f));
}

__device__ __forceinline__ void mma8(float* c, const unsigned* a, const unsigned* b) {
    asm volatile(
        "mma.sync.aligned.m16n8k8.row.col.f32.tf32.tf32.f32 "
        "{%0,%1,%2,%3},{%4,%5,%6,%7},{%8,%9},{%0,%1,%2,%3};\n"
        : "+f"(c[0]), "+f"(c[1]), "+f"(c[2]), "+f"(c[3])
        : "r"(a[0]), "r"(a[1]), "r"(a[2]), "r"(a[3]), "r"(b[0]), "r"(b[1]));
}

__device__ __forceinline__ void cpa16(float* smem_dst, const float* gsrc) {
    unsigned s = (unsigned)__cvta_generic_to_shared(smem_dst);
    asm volatile("cp.async.cg.shared.global [%0], [%1], 16;" :: "r"(s), "l"(gsrc));
}
__device__ __forceinline__ void cpa_commit() {
    asm volatile("cp.async.commit_group;" ::: "memory");
}
__device__ __forceinline__ void cpa_wait1() {
    asm volatile("cp.async.wait_group 1;" ::: "memory");
}
__device__ __forceinline__ void cpa_wait0() {
    asm volatile("cp.async.wait_group 0;" ::: "memory");
}

__device__ __forceinline__ float gelu_tanh_f(float x) {
    float x3 = x * x * x;
    return 0.5f * x * (1.0f + tanhf(0.7978845608028654f * (x + 0.044715f * x3)));
}

__device__ __forceinline__ float block_sum256(float v, float* sh) {
    #pragma unroll
    for (int o = 16; o; o >>= 1) v += __shfl_xor_sync(0xffffffffu, v, o);
    int w = threadIdx.x >> 5;
    if ((threadIdx.x & 31) == 0) sh[w] = v;
    __syncthreads();
    float r = (threadIdx.x < 8) ? sh[threadIdx.x] : 0.0f;
    if (threadIdx.x < 32) {
        #pragma unroll
        for (int o = 4; o; o >>= 1) r += __shfl_xor_sync(0xffffffffu, r, o);
        if (threadIdx.x == 0) sh[0] = r;
    }
    __syncthreads();
    r = sh[0];
    __syncthreads();
    return r;
}

// ---------------------------------------------------------------------------
// Weight pre-rounding: dst[i] = tf32_rna(src[i])  (float4 grid-stride)
// ---------------------------------------------------------------------------
__global__ void __launch_bounds__(256) round_w(
    const float4* __restrict__ src, float4* __restrict__ dst, int n4)
{
    for (int i = blockIdx.x * blockDim.x + threadIdx.x; i < n4;
         i += gridDim.x * blockDim.x) {
        float4 v = src[i];
        v.x = f2tf_f(v.x); v.y = f2tf_f(v.y);
        v.z = f2tf_f(v.z); v.w = f2tf_f(v.w);
        dst[i] = v;
    }
}

// ===========================================================================
// GEMM variant A (round-9 proven): 128x64 tile, 256 threads. Used for PV.
// ===========================================================================
#define GEMM_SMEM_BYTES ((2 * 128 * 36 + 2 * 32 * 72) * 4)

template<int EPI, int CA, int RND>
__device__ __forceinline__ void gemm_body(
    const float* __restrict__ A, const float* __restrict__ Bm,
    float* __restrict__ C, const float* __restrict__ bias,
    int M, int N, int K, int lda, int ldb, int ldc, float* dsm)
{
    float* As = dsm;                 // [2][128][36]
    float* Bs = dsm + 2 * 128 * 36;  // [2][32][72]

    int t = threadIdx.x;
    int lane = t & 31, w = t >> 5;
    int wm = w >> 1, wn = w & 1;
    int lq = lane >> 2, lr = lane & 3;
    int row0 = blockIdx.y * 128, col0 = blockIdx.x * 64;

    float acc[2][4][4];
    #pragma unroll
    for (int i = 0; i < 2; i++)
        #pragma unroll
        for (int j = 0; j < 4; j++)
            #pragma unroll
            for (int l = 0; l < 4; l++) acc[i][j][l] = 0.0f;

    int a_row = t >> 3;             // 0..31 (x4 -> 128)
    int a_kc  = (t & 7) * 4;
    int b_kr  = t >> 4;             // 0..15 (x2 -> 32)
    int b_nc  = (t & 15) * 4;

    #define LOAD_TILES(s, k0)                                                   \
        {                                                                       \
            _Pragma("unroll")                                                   \
            for (int i = 0; i < 4; i++) {                                       \
                int row = a_row + i * 32;                                       \
                cpa16(&As[(s) * 4608 + row * 36 + a_kc],                        \
                      &A[(long)(row0 + row) * lda + (k0) + a_kc]);              \
            }                                                                   \
            _Pragma("unroll")                                                   \
            for (int i = 0; i < 2; i++) {                                       \
                int kr = b_kr + i * 16;                                         \
                cpa16(&Bs[(s) * 2304 + kr * 72 + b_nc],                         \
                      &Bm[(long)((k0) + kr) * ldb + col0 + b_nc]);              \
            }                                                                   \
        }

    LOAD_TILES(0, 0);
    cpa_commit();

    int KT = K >> 5;
    for (int kt = 0; kt < KT; kt++) {
        int cur = kt & 1;
        if (kt + 1 < KT) {
            LOAD_TILES(cur ^ 1, (kt + 1) * 32);
            cpa_commit();
            cpa_wait1();
        } else {
            cpa_wait0();
        }
        __syncthreads();

        const float* Ac = &As[cur * 4608];
        const float* Bc = &Bs[cur * 2304];
        #pragma unroll
        for (int ks = 0; ks < 4; ks++) {
            int kb = ks * 8;
            unsigned a[2][4], bf[4][2];
            #pragma unroll
            for (int mi = 0; mi < 2; mi++) {
                int ar = wm * 32 + mi * 16 + lq;
                if (CA) {
                    a[mi][0] = f2tf(Ac[ar * 36 + kb + lr]);
                    a[mi][1] = f2tf(Ac[(ar + 8) * 36 + kb + lr]);
                    a[mi][2] = f2tf(Ac[ar * 36 + kb + 4 + lr]);
                    a[mi][3] = f2tf(Ac[(ar + 8) * 36 + kb + 4 + lr]);
                } else {
                    a[mi][0] = __float_as_uint(Ac[ar * 36 + kb + lr]);
                    a[mi][1] = __float_as_uint(Ac[(ar + 8) * 36 + kb + lr]);
                    a[mi][2] = __float_as_uint(Ac[ar * 36 + kb + 4 + lr]);
                    a[mi][3] = __float_as_uint(Ac[(ar + 8) * 36 + kb + 4 + lr]);
                }
            }
            #pragma unroll
            for (int nj = 0; nj < 4; nj++) {
                int bn = wn * 32 + nj * 8 + lq;
                bf[nj][0] = __float_as_uint(Bc[(kb + lr) * 72 + bn]);
                bf[nj][1] = __float_as_uint(Bc[(kb + 4 + lr) * 72 + bn]);
            }
            #pragma unroll
            for (int mi = 0; mi < 2; mi++)
                #pragma unroll
                for (int nj = 0; nj < 4; nj++)
                    mma8(acc[mi][nj], a[mi], bf[nj]);
        }
        __syncthreads();
    }
    #undef LOAD_TILES

    #pragma unroll
    for (int mi = 0; mi < 2; mi++) {
        #pragma unroll
        for (int nj = 0; nj < 4; nj++) {
            int r = row0 + wm * 32 + mi * 16 + lq;
            int c = col0 + wn * 32 + nj * 8 + 2 * lr;
            float v0 = acc[mi][nj][0], v1 = acc[mi][nj][1];
            float v2 = acc[mi][nj][2], v3 = acc[mi][nj][3];
            if (EPI >= 1) {
                float b0 = bias[c], b1 = bias[c + 1];
                v0 += b0; v1 += b1; v2 += b0; v3 += b1;
            }
            if (EPI == 2) {
                v0 = gelu_tanh_f(v0); v1 = gelu_tanh_f(v1);
                v2 = gelu_tanh_f(v2); v3 = gelu_tanh_f(v3);
            }
            if (RND) {
                v0 = f2tf_f(v0); v1 = f2tf_f(v1);
                v2 = f2tf_f(v2); v3 = f2tf_f(v3);
            }
            *(float2*)&C[(long)r * ldc + c] = make_float2(v0, v1);
            *(float2*)&C[(long)(r + 8) * ldc + c] = make_float2(v2, v3);
        }
    }
}

template<int EPI, int CA, int RND, int ATTN>
__global__ void __launch_bounds__(256) gemm_tf32(
    const float* __restrict__ A, const float* __restrict__ Bm,
    float* __restrict__ C, const float* __restrict__ bias,
    int M, int N, int K, int lda, int ldb, int ldc)
{
    if (ATTN) {
        int z = blockIdx.z;
        int b = z >> 4;
        int h = z & 15;
        A  += (long)z * SQ * SQ;
        Bm += (long)b * SQ * DM + h * DK;
        C  += (long)b * SQ * DM + h * DK;
    }
    extern __shared__ float dsm[];
    gemm_body<EPI, CA, RND>(A, Bm, C, bias, M, N, K, lda, ldb, ldc, dsm);
}

// ===========================================================================
// GEMM variant B (new): 128x128 tile, 512 threads = 16 warps (4m x 4n),
// warp tile 32x32 (same micro-kernel as variant A -> no spill).
// Single __syncthreads per k-iter: wait -> sync -> issue-next -> compute.
// Bs stride 136 (mod 32 = 8 -> (8*lr+lq) conflict-free fragment loads).
// ===========================================================================
#define GEMM128_SMEM_BYTES ((2 * 128 * 36 + 2 * 32 * 136) * 4)

template<int EPI, int CA, int RND>
__device__ __forceinline__ void gemm128_body(
    const float* __restrict__ A, const float* __restrict__ Bm,
    float* __restrict__ C, const float* __restrict__ bias,
    int K, int lda, int ldb, int ldc, float* dsm)
{
    float* As = dsm;                 // [2][128][36]
    float* Bs = dsm + 2 * 128 * 36;  // [2][32][136]

    int t = threadIdx.x;
    int lane = t & 31, w = t >> 5;   // 16 warps
    int wm = w >> 2, wn = w & 3;     // 4m x 4n
    int lq = lane >> 2, lr = lane & 3;
    int row0 = blockIdx.y * 128, col0 = blockIdx.x * 128;

    float acc[2][4][4];
    #pragma unroll
    for (int i = 0; i < 2; i++)
        #pragma unroll
        for (int j = 0; j < 4; j++)
            #pragma unroll
            for (int l = 0; l < 4; l++) acc[i][j][l] = 0.0f;

    int a_row = t >> 3;             // 0..63 (x2 -> 128)
    int a_kc  = (t & 7) * 4;
    int b_kr  = t >> 5;             // 0..15 (x2 -> 32)
    int b_nc  = (t & 31) * 4;       // 0..124

    #define LOAD_TILES(s, k0)                                                   \
        {                                                                       \
            _Pragma("unroll")                                                   \
            for (int i = 0; i < 2; i++) {                                       \
                int row = a_row + i * 64;                                       \
                cpa16(&As[(s) * 4608 + row * 36 + a_kc],                        \
                      &A[(long)(row0 + row) * lda + (k0) + a_kc]);              \
            }                                                                   \
            _Pragma("unroll")                                                   \
            for (int i = 0; i < 2; i++) {                                       \
                int kr = b_kr + i * 16;                                         \
                cpa16(&Bs[(s) * 4352 + kr * 136 + b_nc],                        \
                      &Bm[(long)((k0) + kr) * ldb + col0 + b_nc]);              \
            }                                                                   \
        }

    LOAD_TILES(0, 0);
    cpa_commit();

    int KT = K >> 5;
    for (int kt = 0; kt < KT; kt++) {
        int cur = kt & 1;
        cpa_wait0();
        __syncthreads();
        if (kt + 1 < KT) {
            LOAD_TILES(cur ^ 1, (kt + 1) * 32);
            cpa_commit();
        }

        const float* Ac = &As[cur * 4608];
        const float* Bc = &Bs[cur * 4352];
        #pragma unroll
        for (int ks = 0; ks < 4; ks++) {
            int kb = ks * 8;
            unsigned a[2][4], bf[4][2];
            #pragma unroll
            for (int mi = 0; mi < 2; mi++) {
                int ar = wm * 32 + mi * 16 + lq;
                if (CA) {
                    a[mi][0] = f2tf(Ac[ar * 36 + kb + lr]);
                    a[mi][1] = f2tf(Ac[(ar + 8) * 36 + kb + lr]);
                    a[mi][2] = f2tf(Ac[ar * 36 + kb + 4 + lr]);
                    a[mi][3] = f2tf(Ac[(ar + 8) * 36 + kb + 4 + lr]);
                } else {
                    a[mi][0] = __float_as_uint(Ac[ar * 36 + kb + lr]);
                    a[mi][1] = __float_as_uint(Ac[(ar + 8) * 36 + kb + lr]);
                    a[mi][2] = __float_as_uint(Ac[ar * 36 + kb + 4 + lr]);
                    a[mi][3] = __float_as_uint(Ac[(ar + 8) * 36 + kb + 4 + lr]);
                }
            }
            #pragma unroll
            for (int nj = 0; nj < 4; nj++) {
                int bn = wn * 32 + nj * 8 + lq;
                bf[nj][0] = __float_as_uint(Bc[(kb + lr) * 136 + bn]);
                bf[nj][1] = __float_as_uint(Bc[(kb + 4 + lr) * 136 + bn]);
            }
            #pragma unroll
            for (int mi = 0; mi < 2; mi++)
                #pragma unroll
                for (int nj = 0; nj < 4; nj++)
                    mma8(acc[mi][nj], a[mi], bf[nj]);
        }
    }
    #undef LOAD_TILES

    #pragma unroll
    for (int mi = 0; mi < 2; mi++) {
        #pragma unroll
        for (int nj = 0; nj < 4; nj++) {
            int r = row0 + wm * 32 + mi * 16 + lq;
            int c = col0 + wn * 32 + nj * 8 + 2 * lr;
            float v0 = acc[mi][nj][0], v1 = acc[mi][nj][1];
            float v2 = acc[mi][nj][2], v3 = acc[mi][nj][3];
            if (EPI >= 1) {
                float b0 = bias[c], b1 = bias[c + 1];
                v0 += b0; v1 += b1; v2 += b0; v3 += b1;
            }
            if (EPI == 2) {
                v0 = gelu_tanh_f(v0); v1 = gelu_tanh_f(v1);
                v2 = gelu_tanh_f(v2); v3 = gelu_tanh_f(v3);
            }
            if (RND) {
                v0 = f2tf_f(v0); v1 = f2tf_f(v1);
                v2 = f2tf_f(v2); v3 = f2tf_f(v3);
            }
            *(float2*)&C[(long)r * ldc + c] = make_float2(v0, v1);
            *(float2*)&C[(long)(r + 8) * ldc + c] = make_float2(v2, v3);
        }
    }
}

template<int EPI, int CA, int RND>
__global__ void __launch_bounds__(512) gemm128_tf32(
    const float* __restrict__ A, const float* __restrict__ Bm,
    float* __restrict__ C, const float* __restrict__ bias,
    int K, int lda, int ldb, int ldc)
{
    extern __shared__ float dsm[];
    gemm128_body<EPI, CA, RND>(A, Bm, C, bias, K, lda, ldb, ldc, dsm);
}

// Merged QKV: blockIdx.z selects which projection; outputs tf32-rounded.
__global__ void __launch_bounds__(512) gemm_qkv(
    const float* __restrict__ A,
    const float* __restrict__ B0, const float* __restrict__ B1,
    const float* __restrict__ B2,
    float* __restrict__ C0, float* __restrict__ C1, float* __restrict__ C2)
{
    extern __shared__ float dsm[];
    int zz = blockIdx.z;
    const float* Bm = (zz == 0) ? B0 : (zz == 1) ? B1 : B2;
    float* C = (zz == 0) ? C0 : (zz == 1) ? C1 : C2;
    gemm128_body<0, 1, 1>(A, Bm, C, nullptr, DM, DM, DM, DM, dsm);
}

// ---------------------------------------------------------------------------
// Fused scores + softmax, v3 (round-9 proven): register-resident scores.
// Block = (z, 16 q-rows) x 1024 keys. 256 threads = 8 warps.
// grid: (SQ/16, B*NH). 2 CTAs/SM (79KB smem).
// ---------------------------------------------------------------------------
#define SC3_SMEM_BYTES ((16 * 68 + 2 * 128 * 68 + 128 + 128 + 1024) * 4)

__global__ void __launch_bounds__(256, 2) attn_scores_softmax(
    const float* __restrict__ q, const float* __restrict__ k,
    const float* __restrict__ bias, const int* __restrict__ mask,
    float* __restrict__ p)
{
    extern __shared__ char smx[];
    unsigned* Qs = (unsigned*)smx;               // [16][68] tf32 bits
    float* Ks   = (float*)(Qs + 16 * 68);        // [2][128][68]
    float* rmax = Ks + 2 * 128 * 68;             // [16][8]
    float* rsum = rmax + 128;                    // [16][8]
    int*   msk  = (int*)(rsum + 128);            // [1024]

    int t = threadIdx.x;
    int lane = t & 31, w = t >> 5;               // 8 warps
    int lq = lane >> 2, lr = lane & 3;
    int z = blockIdx.y, b = z >> 4, h = z & 15;
    int q0 = blockIdx.x * 16;

    const float* qb = q + (long)b * SQ * DM + h * DK;
    const float* kb = k + (long)b * SQ * DM + h * DK;
    const float* bz = bias + (long)z * SQ * SQ;

    int k_row = t >> 4;             // 0..15 (x8 -> 128)
    int k_kc  = (t & 15) * 4;
    #define LOAD_SLAB(s, key0)                                                  \
        {                                                                       \
            _Pragma("unroll")                                                   \
            for (int i = 0; i < 8; i++) {                                       \
                int row = k_row + i * 16;                                       \
                cpa16(&Ks[(s) * 8704 + row * 68 + k_kc],                        \
                      &kb[(long)((key0) + row) * DM + k_kc]);                   \
            }                                                                   \
        }

    LOAD_SLAB(0, 0);
    cpa_commit();

    {
        int row = t >> 4;
        int kc = (t & 15) * 4;
        float4 vq = *(const float4*)&qb[(long)(q0 + row) * DM + kc];
        unsigned* dst = &Qs[row * 68 + kc];
        dst[0] = __float_as_uint(vq.x); dst[1] = __float_as_uint(vq.y);
        dst[2] = __float_as_uint(vq.z); dst[3] = __float_as_uint(vq.w);
    }
    ((int4*)msk)[t] = ((const int4*)(mask + b * SQ))[t];

    float sc[8][8];
    float m0 = -3.4e38f, m1 = -3.4e38f;

    const int c0b = w * 16 + 2 * lr;
    long row_a = (long)(q0 + lq) * SQ;
    long row_b = (long)(q0 + lq + 8) * SQ;

    #pragma unroll
    for (int slab = 0; slab < 8; slab++) {
        int cur = slab & 1;
        int key0 = slab * 128;
        if (slab + 1 < 8) {
            LOAD_SLAB(cur ^ 1, key0 + 128);
            cpa_commit();
        }
        int c0 = key0 + c0b;
        int c1 = c0 + 8;
        float2 B00 = *(const float2*)&bz[row_a + c0];
        float2 B01 = *(const float2*)&bz[row_a + c1];
        float2 B10 = *(const float2*)&bz[row_b + c0];
        float2 B11 = *(const float2*)&bz[row_b + c1];
        if (slab + 1 < 8) cpa_wait1(); else cpa_wait0();
        __syncthreads();

        #pragma unroll
        for (int j = 0; j < 8; j++) sc[slab][j] = 0.0f;

        const float* Kc = &Ks[cur * 8704];
        #pragma unroll
        for (int ks = 0; ks < 8; ks++) {
            int kv = ks * 8;
            unsigned a[4], bf0[2], bf1[2];
            a[0] = Qs[lq * 68 + kv + lr];
            a[1] = Qs[(lq + 8) * 68 + kv + lr];
            a[2] = Qs[lq * 68 + kv + 4 + lr];
            a[3] = Qs[(lq + 8) * 68 + kv + 4 + lr];
            int kn0 = w * 16 + lq;
            bf0[0] = __float_as_uint(Kc[kn0 * 68 + kv + lr]);
            bf0[1] = __float_as_uint(Kc[kn0 * 68 + kv + 4 + lr]);
            bf1[0] = __float_as_uint(Kc[(kn0 + 8) * 68 + kv + lr]);
            bf1[1] = __float_as_uint(Kc[(kn0 + 8) * 68 + kv + 4 + lr]);
            mma8(&sc[slab][0], a, bf0);
            mma8(&sc[slab][4], a, bf1);
        }

        int mk0a = msk[c0], mk0b = msk[c0 + 1];
        int mk1a = msk[c1], mk1b = msk[c1 + 1];
        float v0 = sc[slab][0] * 0.125f + B00.x; if (mk0a == 0) v0 = -9e15f;
        float v1 = sc[slab][1] * 0.125f + B00.y; if (mk0b == 0) v1 = -9e15f;
        float v2 = sc[slab][2] * 0.125f + B10.x; if (mk0a == 0) v2 = -9e15f;
        float v3 = sc[slab][3] * 0.125f + B10.y; if (mk0b == 0) v3 = -9e15f;
        float v4 = sc[slab][4] * 0.125f + B01.x; if (mk1a == 0) v4 = -9e15f;
        float v5 = sc[slab][5] * 0.125f + B01.y; if (mk1b == 0) v5 = -9e15f;
        float v6 = sc[slab][6] * 0.125f + B11.x; if (mk1a == 0) v6 = -9e15f;
        float v7 = sc[slab][7] * 0.125f + B11.y; if (mk1b == 0) v7 = -9e15f;
        sc[slab][0] = v0; sc[slab][1] = v1; sc[slab][2] = v2; sc[slab][3] = v3;
        sc[slab][4] = v4; sc[slab][5] = v5; sc[slab][6] = v6; sc[slab][7] = v7;
        m0 = fmaxf(m0, fmaxf(fmaxf(v0, v1), fmaxf(v4, v5)));
        m1 = fmaxf(m1, fmaxf(fmaxf(v2, v3), fmaxf(v6, v7)));
        __syncthreads();
    }
    #undef LOAD_SLAB

    m0 = fmaxf(m0, __shfl_xor_sync(0xffffffffu, m0, 1));
    m0 = fmaxf(m0, __shfl_xor_sync(0xffffffffu, m0, 2));
    m1 = fmaxf(m1, __shfl_xor_sync(0xffffffffu, m1, 1));
    m1 = fmaxf(m1, __shfl_xor_sync(0xffffffffu, m1, 2));
    if (lr == 0) {
        rmax[lq * 8 + w] = m0;
        rmax[(lq + 8) * 8 + w] = m1;
    }
    __syncthreads();
    float rm0 = rmax[lq * 8];
    float rm1 = rmax[(lq + 8) * 8];
    #pragma unroll
    for (int j = 1; j < 8; j++) {
        rm0 = fmaxf(rm0, rmax[lq * 8 + j]);
        rm1 = fmaxf(rm1, rmax[(lq + 8) * 8 + j]);
    }

    float s0 = 0.0f, s1 = 0.0f;
    #pragma unroll
    for (int slab = 0; slab < 8; slab++) {
        float e0 = __expf(sc[slab][0] - rm0);
        float e1 = __expf(sc[slab][1] - rm0);
        float e4 = __expf(sc[slab][4] - rm0);
        float e5 = __expf(sc[slab][5] - rm0);
        float e2 = __expf(sc[slab][2] - rm1);
        float e3 = __expf(sc[slab][3] - rm1);
        float e6 = __expf(sc[slab][6] - rm1);
        float e7 = __expf(sc[slab][7] - rm1);
        s0 += (e0 + e1) + (e4 + e5);
        s1 += (e2 + e3) + (e6 + e7);
        sc[slab][0] = e0; sc[slab][1] = e1; sc[slab][2] = e2; sc[slab][3] = e3;
        sc[slab][4] = e4; sc[slab][5] = e5; sc[slab][6] = e6; sc[slab][7] = e7;
    }
    s0 += __shfl_xor_sync(0xffffffffu, s0, 1);
    s0 += __shfl_xor_sync(0xffffffffu, s0, 2);
    s1 += __shfl_xor_sync(0xffffffffu, s1, 1);
    s1 += __shfl_xor_sync(0xffffffffu, s1, 2);
    if (lr == 0) {
        rsum[lq * 8 + w] = s0;
        rsum[(lq + 8) * 8 + w] = s1;
    }
    __syncthreads();
    float t0 = 0.0f, t1 = 0.0f;
    #pragma unroll
    for (int j = 0; j < 8; j++) {
        t0 += rsum[lq * 8 + j];
        t1 += rsum[(lq + 8) * 8 + j];
    }
    float inv0 = 1.0f / t0;
    float inv1 = 1.0f / t1;

    float* pr0 = p + (long)z * SQ * SQ + row_a;
    float* pr1 = p + (long)z * SQ * SQ + row_b;
    #pragma unroll
    for (int slab = 0; slab < 8; slab++) {
        int c0 = slab * 128 + c0b;
        int c1 = c0 + 8;
        *(float2*)&pr0[c0] = make_float2(sc[slab][0] * inv0, sc[slab][1] * inv0);
        *(float2*)&pr0[c1] = make_float2(sc[slab][4] * inv0, sc[slab][5] * inv0);
        *(float2*)&pr1[c0] = make_float2(sc[slab][2] * inv1, sc[slab][3] * inv1);
        *(float2*)&pr1[c1] = make_float2(sc[slab][6] * inv1, sc[slab][7] * inv1);
    }
}

// ---------------------------------------------------------------------------
// out = LayerNorm(A + Bx) * g + b   (row length 1024, one block per row)
// ---------------------------------------------------------------------------
__global__ void __launch_bounds__(256) resid_ln(
    const float* __restrict__ A, const float* __restrict__ Bx,
    const float* __restrict__ gw, const float* __restrict__ bw,
    float* __restrict__ out)
{
    __shared__ float sh[8];
    long base = (long)blockIdx.x * DM;
    int t = threadIdx.x;
    float4 a = *(const float4*)&A[base + t * 4];
    float4 b = *(const float4*)&Bx[base + t * 4];
    float4 v = make_float4(a.x + b.x, a.y + b.y, a.z + b.z, a.w + b.w);

    float s = block_sum256(v.x + v.y + v.z + v.w, sh);
    float mu = s * (1.0f / DM);
    float dx = v.x - mu, dy = v.y - mu, dz = v.z - mu, dw = v.w - mu;
    float ss = block_sum256(dx * dx + dy * dy + dz * dz + dw * dw, sh);
    float rstd = rsqrtf(ss * (1.0f / DM) + 1e-6f);

    float4 g4 = *(const float4*)&gw[t * 4];
    float4 b4 = *(const float4*)&bw[t * 4];
    float4 o;
    o.x = dx * rstd * g4.x + b4.x;
    o.y = dy * rstd * g4.y + b4.y;
    o.z = dz * rstd * g4.z + b4.z;
    o.w = dw * rstd * g4.w + b4.w;
    *(float4*)&out[base + t * 4] = o;
}

// ---------------------------------------------------------------------------
// Launch
// ---------------------------------------------------------------------------
extern "C" void kernel_launch(void* const* d_in, const int* in_sizes, int n_in,
                              void* d_out, int out_size)
{
    const float* x_in      = (const float*)d_in[0];
    const int*   mask      = (const int*)  d_in[1];
    const float* attn_bias = (const float*)d_in[2];
    const float* Wq        = (const float*)d_in[3];
    const float* Wk        = (const float*)d_in[4];
    const float* Wv        = (const float*)d_in[5];
    const float* ln1_g     = (const float*)d_in[6];
    const float* ln1_b     = (const float*)d_in[7];
    const float* W1        = (const float*)d_in[8];
    const float* b1        = (const float*)d_in[9];
    const float* W2        = (const float*)d_in[10];
    const float* b2        = (const float*)d_in[11];
    const float* ln2_g     = (const float*)d_in[12];
    const float* ln2_b     = (const float*)d_in[13];

    float* out  = (float*)d_out;
    float* outx = out + (long)NL * BB * NH * SQ * SQ;

    float *gq, *gk, *gv, *gx, *gt, *gh;
    float *wqr, *wkr, *wvr, *w1r, *w2r;
    cudaGetSymbolAddress((void**)&gq, g_q);
    cudaGetSymbolAddress((void**)&gk, g_k);
    cudaGetSymbolAddress((void**)&gv, g_v);
    cudaGetSymbolAddress((void**)&gx, g_x);
    cudaGetSymbolAddress((void**)&gt, g_t);
    cudaGetSymbolAddress((void**)&gh, g_h);
    cudaGetSymbolAddress((void**)&wqr, g_wq);
    cudaGetSymbolAddress((void**)&wkr, g_wk);
    cudaGetSymbolAddress((void**)&wvr, g_wv);
    cudaGetSymbolAddress((void**)&w1r, g_w1);
    cudaGetSymbolAddress((void**)&w2r, g_w2);

    static int smem_set = 0;
    if (!smem_set) {
        cudaFuncSetAttribute(attn_scores_softmax,
                             cudaFuncAttributeMaxDynamicSharedMemorySize, SC3_SMEM_BYTES);
        cudaFuncSetAttribute(gemm_qkv,
                             cudaFuncAttributeMaxDynamicSharedMemorySize, GEMM128_SMEM_BYTES);
        cudaFuncSetAttribute(gemm128_tf32<2, 1, 1>,
                             cudaFuncAttributeMaxDynamicSharedMemorySize, GEMM128_SMEM_BYTES);
        cudaFuncSetAttribute(gemm128_tf32<1, 0, 0>,
                             cudaFuncAttributeMaxDynamicSharedMemorySize, GEMM128_SMEM_BYTES);
        cudaFuncSetAttribute(gemm_tf32<0, 1, 0, 1>,
                             cudaFuncAttributeMaxDynamicSharedMemorySize, GEMM_SMEM_BYTES);
        smem_set = 1;
    }

    // Pre-round all weights to tf32
    round_w<<<2048, 256>>>((const float4*)Wq, (float4*)wqr, NL * DM * DM / 4);
    round_w<<<2048, 256>>>((const float4*)Wk, (float4*)wkr, NL * DM * DM / 4);
    round_w<<<2048, 256>>>((const float4*)Wv, (float4*)wvr, NL * DM * DM / 4);
    round_w<<<2048, 256>>>((const float4*)W1, (float4*)w1r, NL * DM * DFF / 4);
    round_w<<<2048, 256>>>((const float4*)W2, (float4*)w2r, NL * DFF * DM / 4);

    cudaMemcpyAsync(gx, x_in, sizeof(float) * BB * SQ * DM, cudaMemcpyDeviceToDevice);

    const int M = BB * SQ;  // 2048

    for (int n = 0; n < NL; n++) {
        float* p = out + (long)n * BB * NH * SQ * SQ;

        // QKV projections, one merged launch (128x128 tiles); outputs tf32-rounded
        gemm_qkv<<<dim3(8, 16, 3), dim3(512), GEMM128_SMEM_BYTES>>>(
            gx, wqr + (long)n * DM * DM, wkr + (long)n * DM * DM,
            wvr + (long)n * DM * DM, gq, gk, gv);

        // fused scores + softmax -> p (written once)
        attn_scores_softmax<<<dim3(SQ / 16, BB * NH), dim3(256), SC3_SMEM_BYTES>>>(
            gq, gk, attn_bias, mask, p);

        // o = p @ v  (A=p full precision -> CA=1; B=v pre-rounded) [variant A]
        gemm_tf32<0, 1, 0, 1><<<dim3(1, SQ / 128, BB * NH), dim3(256), GEMM_SMEM_BYTES>>>(
            p, gv, gt, nullptr, SQ, DK, SQ, SQ, DM, DM);

        // x = LN(o + x)
        resid_ln<<<M, dim3(256)>>>(gt, gx, ln1_g + (long)n * DM, ln1_b + (long)n * DM, gx);

        // h = gelu(x W1 + b1); h rounded to tf32
        gemm128_tf32<2, 1, 1><<<dim3(16, 16), dim3(512), GEMM128_SMEM_BYTES>>>(
            gx, w1r + (long)n * DM * DFF, gh, b1 + (long)n * DFF,
            DM, DM, DFF, DFF);
        // f = h W2 + b2  (A=h pre-rounded -> CA=0)
        gemm128_tf32<1, 0, 0><<<dim3(8, 16), dim3(512), GEMM128_SMEM_BYTES>>>(
            gh, w2r + (long)n * DFF * DM, gt, b2 + (long)n * DM,
            DFF, DFF, DM, DM);
        // x = LN(x + f)
        resid_ln<<<M, dim3(256)>>>(gx, gt, ln2_g + (long)n * DM, ln2_b + (long)n * DM, gx);
    }

    cudaMemcpyAsync(outx, gx, sizeof(float) * BB * SQ * DM, cudaMemcpyDeviceToDevice);
}

// round 13
// speedup vs baseline: 1.1797x; 1.0096x over previous
#include <cuda_runtime.h>
#include <cuda_bf16.h>
#include <math.h>

// Problem constants
#define BB   2
#define SQ   1024
#define DM   1024
#define NH   16
#define DK   64
#define DFF  2048
#define NL   4

// ---------------------------------------------------------------------------
// Scratch (device globals — no allocation allowed)
// ---------------------------------------------------------------------------
__device__ __align__(16) float g_q[BB * SQ * DM];
__device__ __align__(16) float g_k[BB * SQ * DM];
__device__ __align__(16) float g_v[BB * SQ * DM];
__device__ __align__(16) float g_x[BB * SQ * DM];
__device__ __align__(16) float g_xr[BB * SQ * DM];   // tf32-rounded activations
__device__ __align__(16) float g_t[BB * SQ * DM];
__device__ __align__(16) float g_h[BB * SQ * DFF];
// tf32-pre-rounded, TRANSPOSED weights: [N][K] layout
__device__ __align__(16) float g_wq[NL * DM * DM];
__device__ __align__(16) float g_wk[NL * DM * DM];
__device__ __align__(16) float g_wv[NL * DM * DM];
__device__ __align__(16) float g_w1[NL * DM * DFF];
__device__ __align__(16) float g_w2[NL * DFF * DM];

// ---------------------------------------------------------------------------
// Helpers
// ---------------------------------------------------------------------------
__device__ __forceinline__ unsigned f2tf(float f) {
    unsigned u;
    asm("cvt.rna.tf32.f32 %0, %1;" : "=r"(u) : "f"(f));
    return u;
}
__device__ __forceinline__ float f2tf_f(float f) {
    return __uint_as_float(f2tf(f));
}

__device__ __forceinline__ void mma8(float* c, const unsigned* a, const unsigned* b) {
    asm volatile(
        "mma.sync.aligned.m16n8k8.row.col.f32.tf32.tf32.f32 "
        "{%0,%1,%2,%3},{%4,%5,%6,%7},{%8,%9},{%0,%1,%2,%3};\n"
        : "+f"(c[0]), "+f"(c[1]), "+f"(c[2]), "+f"(c[3])
        : "r"(a[0]), "r"(a[1]), "r"(a[2]), "r"(a[3]), "r"(b[0]), "r"(b[1]));
}

__device__ __forceinline__ void cpa16(float* smem_dst, const float* gsrc) {
    unsigned s = (unsigned)__cvta_generic_to_shared(smem_dst);
    asm volatile("cp.async.cg.shared.global [%0], [%1], 16;" :: "r"(s), "l"(gsrc));
}
__device__ __forceinline__ void cpa_commit() {
    asm volatile("cp.async.commit_group;" ::: "memory");
}
__device__ __forceinline__ void cpa_wait1() {
    asm volatile("cp.async.wait_group 1;" ::: "memory");
}
__device__ __forceinline__ void cpa_wait0() {
    asm volatile("cp.async.wait_group 0;" ::: "memory");
}

__device__ __forceinline__ float gelu_tanh_f(float x) {
    float x3 = x * x * x;
    return 0.5f * x * (1.0f + tanhf(0.7978845608028654f * (x + 0.044715f * x3)));
}

__device__ __forceinline__ float block_sum256(float v, float* sh) {
    #pragma unroll
    for (int o = 16; o; o >>= 1) v += __shfl_xor_sync(0xffffffffu, v, o);
    int w = threadIdx.x >> 5;
    if ((threadIdx.x & 31) == 0) sh[w] = v;
    __syncthreads();
    float r = (threadIdx.x < 8) ? sh[threadIdx.x] : 0.0f;
    if (threadIdx.x < 32) {
        #pragma unroll
        for (int o = 4; o; o >>= 1) r += __shfl_xor_sync(0xffffffffu, r, o);
        if (threadIdx.x == 0) sh[0] = r;
    }
    __syncthreads();
    r = sh[0];
    __syncthreads();
    return r;
}

// ---------------------------------------------------------------------------
// round_w: dst[i] = tf32_rna(src[i])  (float4 grid-stride) — used for x
// ---------------------------------------------------------------------------
__global__ void __launch_bounds__(256) round_w(
    const float4* __restrict__ src, float4* __restrict__ dst, int n4)
{
    for (int i = blockIdx.x * blockDim.x + threadIdx.x; i < n4;
         i += gridDim.x * blockDim.x) {
        float4 v = src[i];
        v.x = f2tf_f(v.x); v.y = f2tf_f(v.y);
        v.z = f2tf_f(v.z); v.w = f2tf_f(v.w);
        dst[i] = v;
    }
}

// ---------------------------------------------------------------------------
// transpose_round: src [z][R][C] -> dst [z][C][R], tf32-rounded.
// block (32,8), grid (C/32, R/32, z)
// ---------------------------------------------------------------------------
__global__ void __launch_bounds__(256) transpose_round(
    const float* __restrict__ src, float* __restrict__ dst, int R, int C)
{
    __shared__ float tile[32][33];
    long zoff = (long)blockIdx.z * R * C;
    const float* s = src + zoff;
    float* d = dst + zoff;
    int tx = threadIdx.x, ty = threadIdx.y;
    int r0 = blockIdx.y * 32, c0 = blockIdx.x * 32;
    #pragma unroll
    for (int i = 0; i < 32; i += 8)
        tile[ty + i][tx] = s[(long)(r0 + ty + i) * C + c0 + tx];
    __syncthreads();
    #pragma unroll
    for (int i = 0; i < 32; i += 8)
        d[(long)(c0 + ty + i) * R + r0 + tx] = f2tf_f(tile[tx][ty + i]);
}

// ===========================================================================
// GEMM variant A (round-9 proven): 128x64 tile, 256 threads. Used for PV.
// B in [K][N] layout. CA=1: cvt.rna A fragments.
// ===========================================================================
#define GEMM_SMEM_BYTES ((2 * 128 * 36 + 2 * 32 * 72) * 4)

__global__ void __launch_bounds__(256) gemm_pv(
    const float* __restrict__ Ain, const float* __restrict__ Bmin,
    float* __restrict__ Cin)
{
    const float* A;
    const float* Bm;
    float* C;
    {
        int z = blockIdx.z;
        int b = z >> 4;
        int h = z & 15;
        A  = Ain + (long)z * SQ * SQ;
        Bm = Bmin + (long)b * SQ * DM + h * DK;
        C  = Cin + (long)b * SQ * DM + h * DK;
    }
    extern __shared__ float dsm[];
    float* As = dsm;                 // [2][128][36]
    float* Bs = dsm + 2 * 128 * 36;  // [2][32][72]

    const int lda = SQ, ldb = DM, ldc = DM, K = SQ;
    int t = threadIdx.x;
    int lane = t & 31, w = t >> 5;
    int wm = w >> 1, wn = w & 1;
    int lq = lane >> 2, lr = lane & 3;
    int row0 = blockIdx.y * 128, col0 = blockIdx.x * 64;

    float acc[2][4][4];
    #pragma unroll
    for (int i = 0; i < 2; i++)
        #pragma unroll
        for (int j = 0; j < 4; j++)
            #pragma unroll
            for (int l = 0; l < 4; l++) acc[i][j][l] = 0.0f;

    int a_row = t >> 3;
    int a_kc  = (t & 7) * 4;
    int b_kr  = t >> 4;
    int b_nc  = (t & 15) * 4;

    #define LOAD_TILES(s, k0)                                                   \
        {                                                                       \
            _Pragma("unroll")                                                   \
            for (int i = 0; i < 4; i++) {                                       \
                int row = a_row + i * 32;                                       \
                cpa16(&As[(s) * 4608 + row * 36 + a_kc],                        \
                      &A[(long)(row0 + row) * lda + (k0) + a_kc]);              \
            }                                                                   \
            _Pragma("unroll")                                                   \
            for (int i = 0; i < 2; i++) {                                       \
                int kr = b_kr + i * 16;                                         \
                cpa16(&Bs[(s) * 2304 + kr * 72 + b_nc],                         \
                      &Bm[(long)((k0) + kr) * ldb + col0 + b_nc]);              \
            }                                                                   \
        }

    LOAD_TILES(0, 0);
    cpa_commit();

    int KT = K >> 5;
    for (int kt = 0; kt < KT; kt++) {
        int cur = kt & 1;
        if (kt + 1 < KT) {
            LOAD_TILES(cur ^ 1, (kt + 1) * 32);
            cpa_commit();
            cpa_wait1();
        } else {
            cpa_wait0();
        }
        __syncthreads();

        const float* Ac = &As[cur * 4608];
        const float* Bc = &Bs[cur * 2304];
        #pragma unroll
        for (int ks = 0; ks < 4; ks++) {
            int kb = ks * 8;
            unsigned a[2][4], bf[4][2];
            #pragma unroll
            for (int mi = 0; mi < 2; mi++) {
                int ar = wm * 32 + mi * 16 + lq;
                a[mi][0] = f2tf(Ac[ar * 36 + kb + lr]);
                a[mi][1] = f2tf(Ac[(ar + 8) * 36 + kb + lr]);
                a[mi][2] = f2tf(Ac[ar * 36 + kb + 4 + lr]);
                a[mi][3] = f2tf(Ac[(ar + 8) * 36 + kb + 4 + lr]);
            }
            #pragma unroll
            for (int nj = 0; nj < 4; nj++) {
                int bn = wn * 32 + nj * 8 + lq;
                bf[nj][0] = __float_as_uint(Bc[(kb + lr) * 72 + bn]);
                bf[nj][1] = __float_as_uint(Bc[(kb + 4 + lr) * 72 + bn]);
            }
            #pragma unroll
            for (int mi = 0; mi < 2; mi++)
                #pragma unroll
                for (int nj = 0; nj < 4; nj++)
                    mma8(acc[mi][nj], a[mi], bf[nj]);
        }
        __syncthreads();
    }
    #undef LOAD_TILES

    #pragma unroll
    for (int mi = 0; mi < 2; mi++) {
        #pragma unroll
        for (int nj = 0; nj < 4; nj++) {
            int r = row0 + wm * 32 + mi * 16 + lq;
            int c = col0 + wn * 32 + nj * 8 + 2 * lr;
            *(float2*)&C[(long)r * ldc + c] =
                make_float2(acc[mi][nj][0], acc[mi][nj][1]);
            *(float2*)&C[(long)(r + 8) * ldc + c] =
                make_float2(acc[mi][nj][2], acc[mi][nj][3]);
        }
    }
}

// ===========================================================================
// GEMM variant C: 128x128 CTA, 128 threads = 4 warps (2x2), warp tile 64x64.
// A [M][K] (pre-rounded), Bt [N][K] transposed (pre-rounded).
// Both smem tiles [128][36] (k-contig), conflict-free (4lq+lr) fragments.
// Smem traffic halved vs 4x4-warp config -> higher TF/s ceiling.
// ===========================================================================
#define G64_SMEM_BYTES ((2 * 128 * 36 + 2 * 128 * 36) * 4)

template<int EPI, int RND>
__device__ __forceinline__ void gemm64_body(
    const float* __restrict__ A, const float* __restrict__ Bt,
    float* __restrict__ C, const float* __restrict__ bias,
    int K, int lda, int ldb, int ldc, float* dsm)
{
    float* As = dsm;                  // [2][128][36]
    float* Bs = dsm + 2 * 128 * 36;   // [2][128][36]

    int t = threadIdx.x;              // 128 threads
    int lane = t & 31, w = t >> 5;    // 4 warps
    int wm = w >> 1, wn = w & 1;      // 2 x 2
    int lq = lane >> 2, lr = lane & 3;
    int row0 = blockIdx.y * 128, col0 = blockIdx.x * 128;

    float acc[4][8][4];
    #pragma unroll
    for (int i = 0; i < 4; i++)
        #pragma unroll
        for (int j = 0; j < 8; j++)
            #pragma unroll
            for (int l = 0; l < 4; l++) acc[i][j][l] = 0.0f;

    int a_row = t >> 3;               // 0..15 (x8 -> 128)
    int a_kc  = (t & 7) * 4;

    #define LOAD_TILES(s, k0)                                                   \
        {                                                                       \
            _Pragma("unroll")                                                   \
            for (int i = 0; i < 8; i++) {                                       \
                int row = a_row + i * 16;                                       \
                cpa16(&As[(s) * 4608 + row * 36 + a_kc],                        \
                      &A[(long)(row0 + row) * lda + (k0) + a_kc]);              \
                cpa16(&Bs[(s) * 4608 + row * 36 + a_kc],                        \
                      &Bt[(long)(col0 + row) * ldb + (k0) + a_kc]);             \
            }                                                                   \
        }

    LOAD_TILES(0, 0);
    cpa_commit();

    int KT = K >> 5;
    for (int kt = 0; kt < KT; kt++) {
        int cur = kt & 1;
        cpa_wait0();
        __syncthreads();
        if (kt + 1 < KT) {
            LOAD_TILES(cur ^ 1, (kt + 1) * 32);
            cpa_commit();
        }

        const float* Ac = &As[cur * 4608];
        const float* Bc = &Bs[cur * 4608];
        #pragma unroll
        for (int ks = 0; ks < 4; ks++) {
            int kb = ks * 8;
            unsigned a[4][4], bf[8][2];
            #pragma unroll
            for (int mi = 0; mi < 4; mi++) {
                int ar = wm * 64 + mi * 16 + lq;
                a[mi][0] = __float_as_uint(Ac[ar * 36 + kb + lr]);
                a[mi][1] = __float_as_uint(Ac[(ar + 8) * 36 + kb + lr]);
                a[mi][2] = __float_as_uint(Ac[ar * 36 + kb + 4 + lr]);
                a[mi][3] = __float_as_uint(Ac[(ar + 8) * 36 + kb + 4 + lr]);
            }
            #pragma unroll
            for (int nj = 0; nj < 8; nj++) {
                int bn = wn * 64 + nj * 8 + lq;
                bf[nj][0] = __float_as_uint(Bc[bn * 36 + kb + lr]);
                bf[nj][1] = __float_as_uint(Bc[bn * 36 + kb + 4 + lr]);
            }
            #pragma unroll
            for (int mi = 0; mi < 4; mi++)
                #pragma unroll
                for (int nj = 0; nj < 8; nj++)
                    mma8(acc[mi][nj], a[mi], bf[nj]);
        }
    }
    #undef LOAD_TILES

    #pragma unroll
    for (int mi = 0; mi < 4; mi++) {
        #pragma unroll
        for (int nj = 0; nj < 8; nj++) {
            int r = row0 + wm * 64 + mi * 16 + lq;
            int c = col0 + wn * 64 + nj * 8 + 2 * lr;
            float v0 = acc[mi][nj][0], v1 = acc[mi][nj][1];
            float v2 = acc[mi][nj][2], v3 = acc[mi][nj][3];
            if (EPI >= 1) {
                float b0 = bias[c], b1 = bias[c + 1];
                v0 += b0; v1 += b1; v2 += b0; v3 += b1;
            }
            if (EPI == 2) {
                v0 = gelu_tanh_f(v0); v1 = gelu_tanh_f(v1);
                v2 = gelu_tanh_f(v2); v3 = gelu_tanh_f(v3);
            }
            if (RND) {
                v0 = f2tf_f(v0); v1 = f2tf_f(v1);
                v2 = f2tf_f(v2); v3 = f2tf_f(v3);
            }
            *(float2*)&C[(long)r * ldc + c] = make_float2(v0, v1);
            *(float2*)&C[(long)(r + 8) * ldc + c] = make_float2(v2, v3);
        }
    }
}

template<int EPI, int RND>
__global__ void __launch_bounds__(128) gemm64_tf32(
    const float* __restrict__ A, const float* __restrict__ Bt,
    float* __restrict__ C, const float* __restrict__ bias,
    int K, int lda, int ldb, int ldc)
{
    extern __shared__ float dsm[];
    gemm64_body<EPI, RND>(A, Bt, C, bias, K, lda, ldb, ldc, dsm);
}

// Merged QKV: blockIdx.z selects projection. Weights transposed [N][K].
__global__ void __launch_bounds__(128) gemm_qkv64(
    const float* __restrict__ A,
    const float* __restrict__ B0, const float* __restrict__ B1,
    const float* __restrict__ B2,
    float* __restrict__ C0, float* __restrict__ C1, float* __restrict__ C2)
{
    extern __shared__ float dsm[];
    int zz = blockIdx.z;
    const float* Bt = (zz == 0) ? B0 : (zz == 1) ? B1 : B2;
    float* C = (zz == 0) ? C0 : (zz == 1) ? C1 : C2;
    gemm64_body<0, 1>(A, Bt, C, nullptr, DM, DM, DM, DM, dsm);
}

// ---------------------------------------------------------------------------
// Fused scores + softmax (round-9 proven): register-resident scores.
// Block = (z, 16 q-rows) x 1024 keys. 256 threads = 8 warps.
// grid: (SQ/16, B*NH). 2 CTAs/SM (79KB smem).
// ---------------------------------------------------------------------------
#define SC3_SMEM_BYTES ((16 * 68 + 2 * 128 * 68 + 128 + 128 + 1024) * 4)

__global__ void __launch_bounds__(256, 2) attn_scores_softmax(
    const float* __restrict__ q, const float* __restrict__ k,
    const float* __restrict__ bias, const int* __restrict__ mask,
    float* __restrict__ p)
{
    extern __shared__ char smx[];
    unsigned* Qs = (unsigned*)smx;               // [16][68] tf32 bits
    float* Ks   = (float*)(Qs + 16 * 68);        // [2][128][68]
    float* rmax = Ks + 2 * 128 * 68;             // [16][8]
    float* rsum = rmax + 128;                    // [16][8]
    int*   msk  = (int*)(rsum + 128);            // [1024]

    int t = threadIdx.x;
    int lane = t & 31, w = t >> 5;               // 8 warps
    int lq = lane >> 2, lr = lane & 3;
    int z = blockIdx.y, b = z >> 4, h = z & 15;
    int q0 = blockIdx.x * 16;

    const float* qb = q + (long)b * SQ * DM + h * DK;
    const float* kb = k + (long)b * SQ * DM + h * DK;
    const float* bz = bias + (long)z * SQ * SQ;

    int k_row = t >> 4;
    int k_kc  = (t & 15) * 4;
    #define LOAD_SLAB(s, key0)                                                  \
        {                                                                       \
            _Pragma("unroll")                                                   \
            for (int i = 0; i < 8; i++) {                                       \
                int row = k_row + i * 16;                                       \
                cpa16(&Ks[(s) * 8704 + row * 68 + k_kc],                        \
                      &kb[(long)((key0) + row) * DM + k_kc]);                   \
            }                                                                   \
        }

    LOAD_SLAB(0, 0);
    cpa_commit();

    {
        int row = t >> 4;
        int kc = (t & 15) * 4;
        float4 vq = *(const float4*)&qb[(long)(q0 + row) * DM + kc];
        unsigned* dst = &Qs[row * 68 + kc];
        dst[0] = __float_as_uint(vq.x); dst[1] = __float_as_uint(vq.y);
        dst[2] = __float_as_uint(vq.z); dst[3] = __float_as_uint(vq.w);
    }
    ((int4*)msk)[t] = ((const int4*)(mask + b * SQ))[t];

    float sc[8][8];
    float m0 = -3.4e38f, m1 = -3.4e38f;

    const int c0b = w * 16 + 2 * lr;
    long row_a = (long)(q0 + lq) * SQ;
    long row_b = (long)(q0 + lq + 8) * SQ;

    #pragma unroll
    for (int slab = 0; slab < 8; slab++) {
        int cur = slab & 1;
        int key0 = slab * 128;
        if (slab + 1 < 8) {
            LOAD_SLAB(cur ^ 1, key0 + 128);
            cpa_commit();
        }
        int c0 = key0 + c0b;
        int c1 = c0 + 8;
        float2 B00 = *(const float2*)&bz[row_a + c0];
        float2 B01 = *(const float2*)&bz[row_a + c1];
        float2 B10 = *(const float2*)&bz[row_b + c0];
        float2 B11 = *(const float2*)&bz[row_b + c1];
        if (slab + 1 < 8) cpa_wait1(); else cpa_wait0();
        __syncthreads();

        #pragma unroll
        for (int j = 0; j < 8; j++) sc[slab][j] = 0.0f;

        const float* Kc = &Ks[cur * 8704];
        #pragma unroll
        for (int ks = 0; ks < 8; ks++) {
            int kv = ks * 8;
            unsigned a[4], bf0[2], bf1[2];
            a[0] = Qs[lq * 68 + kv + lr];
            a[1] = Qs[(lq + 8) * 68 + kv + lr];
            a[2] = Qs[lq * 68 + kv + 4 + lr];
            a[3] = Qs[(lq + 8) * 68 + kv + 4 + lr];
            int kn0 = w * 16 + lq;
            bf0[0] = __float_as_uint(Kc[kn0 * 68 + kv + lr]);
            bf0[1] = __float_as_uint(Kc[kn0 * 68 + kv + 4 + lr]);
            bf1[0] = __float_as_uint(Kc[(kn0 + 8) * 68 + kv + lr]);
            bf1[1] = __float_as_uint(Kc[(kn0 + 8) * 68 + kv + 4 + lr]);
            mma8(&sc[slab][0], a, bf0);
            mma8(&sc[slab][4], a, bf1);
        }

        int mk0a = msk[c0], mk0b = msk[c0 + 1];
        int mk1a = msk[c1], mk1b = msk[c1 + 1];
        float v0 = sc[slab][0] * 0.125f + B00.x; if (mk0a == 0) v0 = -9e15f;
        float v1 = sc[slab][1] * 0.125f + B00.y; if (mk0b == 0) v1 = -9e15f;
        float v2 = sc[slab][2] * 0.125f + B10.x; if (mk0a == 0) v2 = -9e15f;
        float v3 = sc[slab][3] * 0.125f + B10.y; if (mk0b == 0) v3 = -9e15f;
        float v4 = sc[slab][4] * 0.125f + B01.x; if (mk1a == 0) v4 = -9e15f;
        float v5 = sc[slab][5] * 0.125f + B01.y; if (mk1b == 0) v5 = -9e15f;
        float v6 = sc[slab][6] * 0.125f + B11.x; if (mk1a == 0) v6 = -9e15f;
        float v7 = sc[slab][7] * 0.125f + B11.y; if (mk1b == 0) v7 = -9e15f;
        sc[slab][0] = v0; sc[slab][1] = v1; sc[slab][2] = v2; sc[slab][3] = v3;
        sc[slab][4] = v4; sc[slab][5] = v5; sc[slab][6] = v6; sc[slab][7] = v7;
        m0 = fmaxf(m0, fmaxf(fmaxf(v0, v1), fmaxf(v4, v5)));
        m1 = fmaxf(m1, fmaxf(fmaxf(v2, v3), fmaxf(v6, v7)));
        __syncthreads();
    }
    #undef LOAD_SLAB

    m0 = fmaxf(m0, __shfl_xor_sync(0xffffffffu, m0, 1));
    m0 = fmaxf(m0, __shfl_xor_sync(0xffffffffu, m0, 2));
    m1 = fmaxf(m1, __shfl_xor_sync(0xffffffffu, m1, 1));
    m1 = fmaxf(m1, __shfl_xor_sync(0xffffffffu, m1, 2));
    if (lr == 0) {
        rmax[lq * 8 + w] = m0;
        rmax[(lq + 8) * 8 + w] = m1;
    }
    __syncthreads();
    float rm0 = rmax[lq * 8];
    float rm1 = rmax[(lq + 8) * 8];
    #pragma unroll
    for (int j = 1; j < 8; j++) {
        rm0 = fmaxf(rm0, rmax[lq * 8 + j]);
        rm1 = fmaxf(rm1, rmax[(lq + 8) * 8 + j]);
    }

    float s0 = 0.0f, s1 = 0.0f;
    #pragma unroll
    for (int slab = 0; slab < 8; slab++) {
        float e0 = __expf(sc[slab][0] - rm0);
        float e1 = __expf(sc[slab][1] - rm0);
        float e4 = __expf(sc[slab][4] - rm0);
        float e5 = __expf(sc[slab][5] - rm0);
        float e2 = __expf(sc[slab][2] - rm1);
        float e3 = __expf(sc[slab][3] - rm1);
        float e6 = __expf(sc[slab][6] - rm1);
        float e7 = __expf(sc[slab][7] - rm1);
        s0 += (e0 + e1) + (e4 + e5);
        s1 += (e2 + e3) + (e6 + e7);
        sc[slab][0] = e0; sc[slab][1] = e1; sc[slab][2] = e2; sc[slab][3] = e3;
        sc[slab][4] = e4; sc[slab][5] = e5; sc[slab][6] = e6; sc[slab][7] = e7;
    }
    s0 += __shfl_xor_sync(0xffffffffu, s0, 1);
    s0 += __shfl_xor_sync(0xffffffffu, s0, 2);
    s1 += __shfl_xor_sync(0xffffffffu, s1, 1);
    s1 += __shfl_xor_sync(0xffffffffu, s1, 2);
    if (lr == 0) {
        rsum[lq * 8 + w] = s0;
        rsum[(lq + 8) * 8 + w] = s1;
    }
    __syncthreads();
    float t0 = 0.0f, t1 = 0.0f;
    #pragma unroll
    for (int j = 0; j < 8; j++) {
        t0 += rsum[lq * 8 + j];
        t1 += rsum[(lq + 8) * 8 + j];
    }
    float inv0 = 1.0f / t0;
    float inv1 = 1.0f / t1;

    float* pr0 = p + (long)z * SQ * SQ + row_a;
    float* pr1 = p + (long)z * SQ * SQ + row_b;
    #pragma unroll
    for (int slab = 0; slab < 8; slab++) {
        int c0 = slab * 128 + c0b;
        int c1 = c0 + 8;
        *(float2*)&pr0[c0] = make_float2(sc[slab][0] * inv0, sc[slab][1] * inv0);
        *(float2*)&pr0[c1] = make_float2(sc[slab][4] * inv0, sc[slab][5] * inv0);
        *(float2*)&pr1[c0] = make_float2(sc[slab][2] * inv1, sc[slab][3] * inv1);
        *(float2*)&pr1[c1] = make_float2(sc[slab][6] * inv1, sc[slab][7] * inv1);
    }
}

// ---------------------------------------------------------------------------
// resid_ln: out = LayerNorm(A + Bx)*g + b (full) ; out_r = tf32_rna(out)
// ---------------------------------------------------------------------------
__global__ void __launch_bounds__(256) resid_ln(
    const float* __restrict__ A, const float* __restrict__ Bx,
    const float* __restrict__ gw, const float* __restrict__ bw,
    float* __restrict__ out, float* __restrict__ out_r)
{
    __shared__ float sh[8];
    long base = (long)blockIdx.x * DM;
    int t = threadIdx.x;
    float4 a = *(const float4*)&A[base + t * 4];
    float4 b = *(const float4*)&Bx[base + t * 4];
    float4 v = make_float4(a.x + b.x, a.y + b.y, a.z + b.z, a.w + b.w);

    float s = block_sum256(v.x + v.y + v.z + v.w, sh);
    float mu = s * (1.0f / DM);
    float dx = v.x - mu, dy = v.y - mu, dz = v.z - mu, dw = v.w - mu;
    float ss = block_sum256(dx * dx + dy * dy + dz * dz + dw * dw, sh);
    float rstd = rsqrtf(ss * (1.0f / DM) + 1e-6f);

    float4 g4 = *(const float4*)&gw[t * 4];
    float4 b4 = *(const float4*)&bw[t * 4];
    float4 o;
    o.x = dx * rstd * g4.x + b4.x;
    o.y = dy * rstd * g4.y + b4.y;
    o.z = dz * rstd * g4.z + b4.z;
    o.w = dw * rstd * g4.w + b4.w;
    *(float4*)&out[base + t * 4] = o;
    float4 orr = make_float4(f2tf_f(o.x), f2tf_f(o.y), f2tf_f(o.z), f2tf_f(o.w));
    *(float4*)&out_r[base + t * 4] = orr;
}

// ---------------------------------------------------------------------------
// Launch
// ---------------------------------------------------------------------------
extern "C" void kernel_launch(void* const* d_in, const int* in_sizes, int n_in,
                              void* d_out, int out_size)
{
    const float* x_in      = (const float*)d_in[0];
    const int*   mask      = (const int*)  d_in[1];
    const float* attn_bias = (const float*)d_in[2];
    const float* Wq        = (const float*)d_in[3];
    const float* Wk        = (const float*)d_in[4];
    const float* Wv        = (const float*)d_in[5];
    const float* ln1_g     = (const float*)d_in[6];
    const float* ln1_b     = (const float*)d_in[7];
    const float* W1        = (const float*)d_in[8];
    const float* b1        = (const float*)d_in[9];
    const float* W2        = (const float*)d_in[10];
    const float* b2        = (const float*)d_in[11];
    const float* ln2_g     = (const float*)d_in[12];
    const float* ln2_b     = (const float*)d_in[13];

    float* out  = (float*)d_out;
    float* outx = out + (long)NL * BB * NH * SQ * SQ;

    float *gq, *gk, *gv, *gx, *gxr, *gt, *gh;
    float *wqT, *wkT, *wvT, *w1T, *w2T;
    cudaGetSymbolAddress((void**)&gq, g_q);
    cudaGetSymbolAddress((void**)&gk, g_k);
    cudaGetSymbolAddress((void**)&gv, g_v);
    cudaGetSymbolAddress((void**)&gx, g_x);
    cudaGetSymbolAddress((void**)&gxr, g_xr);
    cudaGetSymbolAddress((void**)&gt, g_t);
    cudaGetSymbolAddress((void**)&gh, g_h);
    cudaGetSymbolAddress((void**)&wqT, g_wq);
    cudaGetSymbolAddress((void**)&wkT, g_wk);
    cudaGetSymbolAddress((void**)&wvT, g_wv);
    cudaGetSymbolAddress((void**)&w1T, g_w1);
    cudaGetSymbolAddress((void**)&w2T, g_w2);

    static int smem_set = 0;
    if (!smem_set) {
        cudaFuncSetAttribute(attn_scores_softmax,
                             cudaFuncAttributeMaxDynamicSharedMemorySize, SC3_SMEM_BYTES);
        cudaFuncSetAttribute(gemm_qkv64,
                             cudaFuncAttributeMaxDynamicSharedMemorySize, G64_SMEM_BYTES);
        cudaFuncSetAttribute(gemm64_tf32<2, 1>,
                             cudaFuncAttributeMaxDynamicSharedMemorySize, G64_SMEM_BYTES);
        cudaFuncSetAttribute(gemm64_tf32<1, 0>,
                             cudaFuncAttributeMaxDynamicSharedMemorySize, G64_SMEM_BYTES);
        cudaFuncSetAttribute(gemm_pv,
                             cudaFuncAttributeMaxDynamicSharedMemorySize, GEMM_SMEM_BYTES);
        smem_set = 1;
    }

    // Pre-process: transpose+round weights to [N][K]; round x
    {
        dim3 tb(32, 8);
        transpose_round<<<dim3(DM / 32, DM / 32, NL), tb>>>(Wq, wqT, DM, DM);
        transpose_round<<<dim3(DM / 32, DM / 32, NL), tb>>>(Wk, wkT, DM, DM);
        transpose_round<<<dim3(DM / 32, DM / 32, NL), tb>>>(Wv, wvT, DM, DM);
        transpose_round<<<dim3(DFF / 32, DM / 32, NL), tb>>>(W1, w1T, DM, DFF);
        transpose_round<<<dim3(DM / 32, DFF / 32, NL), tb>>>(W2, w2T, DFF, DM);
        round_w<<<512, 256>>>((const float4*)x_in, (float4*)gxr, BB * SQ * DM / 4);
    }

    cudaMemcpyAsync(gx, x_in, sizeof(float) * BB * SQ * DM, cudaMemcpyDeviceToDevice);

    const int M = BB * SQ;  // 2048

    for (int n = 0; n < NL; n++) {
        float* p = out + (long)n * BB * NH * SQ * SQ;

        // QKV projections (A = rounded activations, Bt transposed weights)
        gemm_qkv64<<<dim3(8, 16, 3), dim3(128), G64_SMEM_BYTES>>>(
            gxr, wqT + (long)n * DM * DM, wkT + (long)n * DM * DM,
            wvT + (long)n * DM * DM, gq, gk, gv);

        // fused scores + softmax -> p (written once)
        attn_scores_softmax<<<dim3(SQ / 16, BB * NH), dim3(256), SC3_SMEM_BYTES>>>(
            gq, gk, attn_bias, mask, p);

        // o = p @ v (A=p full precision, cvt at fragment load)
        gemm_pv<<<dim3(1, SQ / 128, BB * NH), dim3(256), GEMM_SMEM_BYTES>>>(
            p, gv, gt);

        // x = LN(o + x)  (full + rounded)
        resid_ln<<<M, dim3(256)>>>(gt, gx,
            ln1_g + (long)n * DM, ln1_b + (long)n * DM, gx, gxr);

        // h = gelu(x W1 + b1); h rounded
        gemm64_tf32<2, 1><<<dim3(16, 16), dim3(128), G64_SMEM_BYTES>>>(
            gxr, w1T + (long)n * DM * DFF, gh, b1 + (long)n * DFF,
            DM, DM, DM, DFF);

        // f = h W2 + b2
        gemm64_tf32<1, 0><<<dim3(8, 16), dim3(128), G64_SMEM_BYTES>>>(
            gh, w2T + (long)n * DFF * DM, gt, b2 + (long)n * DM,
            DFF, DFF, DFF, DM);

        // x = LN(x + f)  (full + rounded)
        resid_ln<<<M, dim3(256)>>>(gx, gt,
            ln2_g + (long)n * DM, ln2_b + (long)n * DM, gx, gxr);
    }

    cudaMemcpyAsync(outx, gx, sizeof(float) * BB * SQ * DM, cudaMemcpyDeviceToDevice);
}